// round 2
// baseline (speedup 1.0000x reference)
#include <cuda_runtime.h>
#include <cuda_bf16.h>
#include <mma.h>
#include <cstdint>

using namespace nvcuda;
typedef __nv_bfloat16 bf16;

#define CB 8192
#define CT 30
#define CD 256
#define CL 6

// ---------------- scratch (static device arrays; no runtime alloc) ----------
__device__ bf16  g_canvas[CB*384];
__device__ bf16  g_t1[CB*512];
__device__ bf16  g_t2b[CB*512];
__device__ bf16  g_cv[CB*256];
__device__ float g_ss[CB*512];
__device__ float g_x[CB*CT*CD];          // fp32 residual stream
__device__ bf16  g_x2[CB*CT*CD];         // modulated LN out / attention out
__device__ bf16  g_qkv[CB*CT*768];
__device__ bf16  g_ffh[CB*CT*1024];
__device__ bf16  g_xin[CB*304];          // flow-matching input, K padded 296->304
__device__ float g_part[64];

__device__ bf16 g_ce_w1[512*384];
__device__ bf16 g_ce_w2[256*512];
__device__ bf16 g_ad1[CL*512*256];
__device__ bf16 g_inp[CL*768*256];
__device__ bf16 g_outp[CL*256*256];
__device__ bf16 g_ad2[CL*512*256];
__device__ bf16 g_ff1[CL*1024*256];
__device__ bf16 g_ff2[CL*256*1024];
__device__ bf16 g_fw1[512*304];
__device__ bf16 g_fw2[512*512];

// ---------------- converts ----------------
__global__ void k_convert(const float* __restrict__ s, bf16* __restrict__ d, int n) {
    int i = blockIdx.x * 256 + threadIdx.x;
    if (i < n) d[i] = __float2bfloat16(s[i]);
}
__global__ void k_convert_pad(const float* __restrict__ s, bf16* __restrict__ d) {
    int i = blockIdx.x * 256 + threadIdx.x;
    if (i >= 512 * 304) return;
    int r = i / 304, k = i % 304;
    d[i] = (k < 296) ? __float2bfloat16(s[r * 296 + k]) : __float2bfloat16(0.f);
}

// ---------------- generic bf16 GEMM: C = A(MxK) @ W(NxK)^T + bias ----------
// EPI: 0 bias->bf16 ; 1 bias+silu->bf16 ; 2 bias+residual add into fp32 ; 3 bias->fp32
template<int EPI>
__launch_bounds__(128)
__global__ void k_gemm(const bf16* __restrict__ A, const bf16* __restrict__ W,
                       const float* __restrict__ bias, bf16* __restrict__ outb,
                       float* __restrict__ outf, int M, int N, int K)
{
    __shared__ bf16 As[64 * 40];
    __shared__ bf16 Ws[64 * 40];
    __shared__ float Cs[4][32 * 36];

    const int tid = threadIdx.x;
    const int wid = tid >> 5;
    const int lane = tid & 31;
    const int m0 = blockIdx.x * 64;
    const int n0 = blockIdx.y * 64;
    const int wm = (wid >> 1) * 32;
    const int wn = (wid & 1) * 32;

    wmma::fragment<wmma::accumulator, 16, 16, 16, float> acc[2][2];
    #pragma unroll
    for (int i = 0; i < 2; i++)
        #pragma unroll
        for (int j = 0; j < 2; j++) wmma::fill_fragment(acc[i][j], 0.f);

    for (int k0 = 0; k0 < K; k0 += 32) {
        #pragma unroll
        for (int c = tid; c < 256; c += 128) {
            int row = c >> 2;
            int kc  = (c & 3) * 8;
            int k   = k0 + kc;
            uint4 va = make_uint4(0u,0u,0u,0u);
            int m = m0 + row;
            if (m < M && k < K) va = *(const uint4*)(A + (size_t)m * K + k);
            *(uint4*)(As + row * 40 + kc) = va;
            uint4 vw = make_uint4(0u,0u,0u,0u);
            int n = n0 + row;
            if (n < N && k < K) vw = *(const uint4*)(W + (size_t)n * K + k);
            *(uint4*)(Ws + row * 40 + kc) = vw;
        }
        __syncthreads();
        #pragma unroll
        for (int kk = 0; kk < 32; kk += 16) {
            wmma::fragment<wmma::matrix_a, 16, 16, 16, bf16, wmma::row_major> af[2];
            wmma::fragment<wmma::matrix_b, 16, 16, 16, bf16, wmma::col_major> bfb[2];
            #pragma unroll
            for (int i = 0; i < 2; i++)
                wmma::load_matrix_sync(af[i], As + (wm + i * 16) * 40 + kk, 40);
            #pragma unroll
            for (int j = 0; j < 2; j++)
                wmma::load_matrix_sync(bfb[j], Ws + (wn + j * 16) * 40 + kk, 40);
            #pragma unroll
            for (int i = 0; i < 2; i++)
                #pragma unroll
                for (int j = 0; j < 2; j++)
                    wmma::mma_sync(acc[i][j], af[i], bfb[j], acc[i][j]);
        }
        __syncthreads();
    }

    #pragma unroll
    for (int i = 0; i < 2; i++)
        #pragma unroll
        for (int j = 0; j < 2; j++)
            wmma::store_matrix_sync(&Cs[wid][(i * 16) * 36 + j * 16], acc[i][j], 36,
                                    wmma::mem_row_major);
    __syncwarp();
    #pragma unroll
    for (int idx = lane; idx < 32 * 32; idx += 32) {
        int r  = idx >> 5;
        int cc = idx & 31;
        int m = m0 + wm + r;
        int n = n0 + wn + cc;
        if (m < M && n < N) {
            float v = Cs[wid][r * 36 + cc] + bias[n];
            if (EPI == 1) v = v / (1.f + __expf(-v));
            if (EPI == 2)      outf[(size_t)m * N + n] += v;
            else if (EPI == 3) outf[(size_t)m * N + n]  = v;
            else               outb[(size_t)m * N + n]  = __float2bfloat16(v);
        }
    }
}

// ---------------- stroke embedding ----------------
__global__ void k_semb(const float* __restrict__ strokes, const float* __restrict__ sp_w,
                       const float* __restrict__ sp_b, const float* __restrict__ pos,
                       float* __restrict__ x)
{
    int row = blockIdx.x;
    int t = row % CT;
    __shared__ float st[8];
    if (threadIdx.x < 8) st[threadIdx.x] = strokes[(size_t)row * 8 + threadIdx.x];
    __syncthreads();
    int d = threadIdx.x;
    float acc = sp_b[d] + pos[t * CD + d];
    #pragma unroll
    for (int s = 0; s < 8; s++) acc += st[s] * sp_w[d * 8 + s];
    x[(size_t)row * CD + d] = acc;
}

// ---------------- adaLN modulate: x2 = (1+sc)*ln(x)+sh ----------------
__global__ void k_mod(const float* __restrict__ x, const float* __restrict__ ss,
                      bf16* __restrict__ x2)
{
    int row = blockIdx.x * 8 + (threadIdx.x >> 5);
    if (row >= CB * CT) return;
    int lane = threadIdx.x & 31;
    int b = row / CT;
    const float* xr = x + (size_t)row * CD;
    float vals[8], s = 0.f, s2 = 0.f;
    #pragma unroll
    for (int i = 0; i < 8; i++) {
        float v = xr[lane + i * 32];
        vals[i] = v; s += v; s2 += v * v;
    }
    #pragma unroll
    for (int sh = 16; sh; sh >>= 1) {
        s  += __shfl_xor_sync(0xffffffffu, s, sh);
        s2 += __shfl_xor_sync(0xffffffffu, s2, sh);
    }
    float mean = s * (1.f / 256.f);
    float var  = s2 * (1.f / 256.f) - mean * mean;
    float rinv = rsqrtf(var + 1e-5f);
    const float* ssb = ss + (size_t)b * 512;
    #pragma unroll
    for (int i = 0; i < 8; i++) {
        int d = lane + i * 32;
        float xn = (vals[i] - mean) * rinv;
        x2[(size_t)row * CD + d] = __float2bfloat16((1.f + ssb[d]) * xn + ssb[256 + d]);
    }
}

// ---------------- attention: one CTA (128 thr) per (b,h) -------------------
__global__ void k_attn(const bf16* __restrict__ qkv, bf16* __restrict__ o)
{
    int bh = blockIdx.x;
    int b = bh >> 3, h = bh & 7;
    __shared__ float sq[CT][33], sk[CT][33], sv[CT][33], sp[CT][33];
    int tid = threadIdx.x;
    size_t base = (size_t)b * CT * 768 + h * 32;
    for (int idx = tid; idx < CT * 32; idx += 128) {
        int t = idx >> 5, d = idx & 31;
        size_t p = base + (size_t)t * 768 + d;
        sq[t][d] = __bfloat162float(qkv[p]);
        sk[t][d] = __bfloat162float(qkv[p + 256]);
        sv[t][d] = __bfloat162float(qkv[p + 512]);
    }
    __syncthreads();
    const float scale = 0.17677669529663687f;
    for (int idx = tid; idx < CT * CT; idx += 128) {
        int i = idx / CT, j = idx % CT;
        if (j <= i) {
            float s = 0.f;
            #pragma unroll
            for (int d = 0; d < 32; d++) s += sq[i][d] * sk[j][d];
            sp[i][j] = s * scale;
        }
    }
    __syncthreads();
    int lane = tid & 31, w = tid >> 5;
    for (int i = w; i < CT; i += 4) {
        float v = (lane <= i) ? sp[i][lane] : -1e30f;
        float mx = v;
        #pragma unroll
        for (int s = 16; s; s >>= 1) mx = fmaxf(mx, __shfl_xor_sync(0xffffffffu, mx, s));
        float e = (lane <= i) ? __expf(v - mx) : 0.f;
        float sum = e;
        #pragma unroll
        for (int s = 16; s; s >>= 1) sum += __shfl_xor_sync(0xffffffffu, sum, s);
        if (lane <= i) sp[i][lane] = e / sum;
    }
    __syncthreads();
    for (int idx = tid; idx < CT * 32; idx += 128) {
        int i = idx >> 5, d = idx & 31;
        float s = 0.f;
        for (int j = 0; j <= i; j++) s += sp[i][j] * sv[j][d];
        o[(size_t)(b * CT + i) * CD + h * 32 + d] = __float2bfloat16(s);
    }
}

// ---------------- final LN + build flow-matching input ---------------------
__global__ void k_final(const float* __restrict__ x, const float* __restrict__ on_g,
                        const float* __restrict__ on_b, const float* __restrict__ a_tar,
                        const float* __restrict__ a_src, const float* __restrict__ t,
                        bf16* __restrict__ xin)
{
    int b = blockIdx.x;
    const float* xr = x + ((size_t)b * CT + 29) * CD;
    __shared__ float rbuf[2][8];
    __shared__ float stats[2];
    int tid = threadIdx.x;
    float v = xr[tid];
    float s = v, s2 = v * v;
    #pragma unroll
    for (int sh = 16; sh; sh >>= 1) {
        s  += __shfl_xor_sync(0xffffffffu, s, sh);
        s2 += __shfl_xor_sync(0xffffffffu, s2, sh);
    }
    if ((tid & 31) == 0) { rbuf[0][tid >> 5] = s; rbuf[1][tid >> 5] = s2; }
    __syncthreads();
    if (tid == 0) {
        float a = 0.f, q = 0.f;
        #pragma unroll
        for (int i = 0; i < 8; i++) { a += rbuf[0][i]; q += rbuf[1][i]; }
        float mean = a * (1.f / 256.f);
        float var  = q * (1.f / 256.f) - mean * mean;
        stats[0] = mean;
        stats[1] = rsqrtf(var + 1e-5f);
    }
    __syncthreads();
    float hn = (v - stats[0]) * stats[1] * on_g[tid] + on_b[tid];
    xin[(size_t)b * 304 + tid] = __float2bfloat16(hn);
    if (tid < 48) {
        int c = 256 + tid;
        float tv = t[b];
        float ov = 0.f;
        if (c < 264) {
            int i = c - 256;
            ov = (1.f - tv) * a_src[b * 8 + i] + tv * a_tar[b * 8 + i];
        } else if (c < 296) {
            int i = c - 264;
            int j = (i < 16) ? i : i - 16;
            float f = __expf(-9.210340371976184f * (float)j / 15.f);
            float a = tv * f;
            ov = (i < 16) ? sinf(a) : cosf(a);
        }
        xin[(size_t)b * 304 + c] = __float2bfloat16(ov);
    }
}

// ---------------- fm3 + loss partials --------------------------------------
__global__ void k_fm3(const bf16* __restrict__ t2, const float* __restrict__ w3,
                      const float* __restrict__ b3, const float* __restrict__ a_tar,
                      const float* __restrict__ a_src, float* __restrict__ part)
{
    __shared__ float sw3[8 * 512];
    int tid = threadIdx.x;
    for (int i = tid; i < 8 * 512; i += 256) sw3[i] = w3[i];
    __syncthreads();
    int b = blockIdx.x * 256 + tid;
    float acc[8];
    #pragma unroll
    for (int o = 0; o < 8; o++) acc[o] = b3[o];
    const bf16* tr = t2 + (size_t)b * 512;
    for (int k = 0; k < 512; k++) {
        float tv = __bfloat162float(tr[k]);
        #pragma unroll
        for (int o = 0; o < 8; o++) acc[o] += tv * sw3[o * 512 + k];
    }
    float local = 0.f;
    #pragma unroll
    for (int o = 0; o < 8; o++) {
        float u = a_tar[b * 8 + o] - a_src[b * 8 + o];
        float d = acc[o] - u;
        local += d * d;
    }
    local *= (1.f / 65536.f);
    #pragma unroll
    for (int sh = 16; sh; sh >>= 1) local += __shfl_xor_sync(0xffffffffu, local, sh);
    __shared__ float rb[8];
    if ((tid & 31) == 0) rb[tid >> 5] = local;
    __syncthreads();
    if (tid == 0) {
        float s = 0.f;
        #pragma unroll
        for (int i = 0; i < 8; i++) s += rb[i];
        part[blockIdx.x] = s;
    }
}

__global__ void k_reduce(const float* __restrict__ part, float* __restrict__ out)
{
    float s = part[threadIdx.x];
    #pragma unroll
    for (int sh = 16; sh; sh >>= 1) s += __shfl_xor_sync(0xffffffffu, s, sh);
    if (threadIdx.x == 0) out[0] = s;
}

// ---------------- host side ------------------------------------------------
static void launch_gemm(int epi, const bf16* A, const bf16* W, const float* bias,
                        bf16* ob, float* of, int M, int N, int K)
{
    dim3 g((M + 63) / 64, (N + 63) / 64);
    switch (epi) {
        case 0: k_gemm<0><<<g, 128>>>(A, W, bias, ob, of, M, N, K); break;
        case 1: k_gemm<1><<<g, 128>>>(A, W, bias, ob, of, M, N, K); break;
        case 2: k_gemm<2><<<g, 128>>>(A, W, bias, ob, of, M, N, K); break;
        default: k_gemm<3><<<g, 128>>>(A, W, bias, ob, of, M, N, K); break;
    }
}

#define GETSYM(var, sym) do { void* _p; cudaGetSymbolAddress(&_p, sym); var = (decltype(var))_p; } while (0)

extern "C" void kernel_launch(void* const* d_in, const int* in_sizes, int n_in,
                              void* d_out, int out_size)
{
    const float* strokes    = (const float*)d_in[0];
    const float* canvas     = (const float*)d_in[1];
    const float* a_tar      = (const float*)d_in[2];
    const float* a_src      = (const float*)d_in[3];
    const float* t_in       = (const float*)d_in[4];
    const float* ce_w1      = (const float*)d_in[5];
    const float* ce_b1      = (const float*)d_in[6];
    const float* ce_w2      = (const float*)d_in[7];
    const float* ce_b2      = (const float*)d_in[8];
    const float* sp_w       = (const float*)d_in[9];
    const float* sp_b       = (const float*)d_in[10];
    const float* pos_emb    = (const float*)d_in[11];
    const float* adaln1_w   = (const float*)d_in[12];
    const float* adaln1_b   = (const float*)d_in[13];
    const float* inproj_w   = (const float*)d_in[14];
    const float* inproj_b   = (const float*)d_in[15];
    const float* outproj_w  = (const float*)d_in[16];
    const float* outproj_b  = (const float*)d_in[17];
    const float* adaln2_w   = (const float*)d_in[18];
    const float* adaln2_b   = (const float*)d_in[19];
    const float* ff1_w      = (const float*)d_in[20];
    const float* ff1_b      = (const float*)d_in[21];
    const float* ff2_w      = (const float*)d_in[22];
    const float* ff2_b      = (const float*)d_in[23];
    const float* on_g       = (const float*)d_in[24];
    const float* on_b       = (const float*)d_in[25];
    const float* fm_w1      = (const float*)d_in[26];
    const float* fm_b1      = (const float*)d_in[27];
    const float* fm_w2      = (const float*)d_in[28];
    const float* fm_b2      = (const float*)d_in[29];
    const float* fm_w3      = (const float*)d_in[30];
    const float* fm_b3      = (const float*)d_in[31];
    float* out = (float*)d_out;
    (void)in_sizes; (void)n_in; (void)out_size;

    bf16 *p_canvas, *p_t1, *p_t2, *p_cv, *p_x2, *p_qkv, *p_ffh, *p_xin;
    bf16 *p_cew1, *p_cew2, *p_ad1, *p_inp, *p_outp, *p_ad2, *p_ff1, *p_ff2, *p_fw1, *p_fw2;
    float *p_ss, *p_x, *p_part;
    GETSYM(p_canvas, g_canvas); GETSYM(p_t1, g_t1); GETSYM(p_t2, g_t2b);
    GETSYM(p_cv, g_cv); GETSYM(p_x2, g_x2); GETSYM(p_qkv, g_qkv);
    GETSYM(p_ffh, g_ffh); GETSYM(p_xin, g_xin);
    GETSYM(p_cew1, g_ce_w1); GETSYM(p_cew2, g_ce_w2); GETSYM(p_ad1, g_ad1);
    GETSYM(p_inp, g_inp); GETSYM(p_outp, g_outp); GETSYM(p_ad2, g_ad2);
    GETSYM(p_ff1, g_ff1); GETSYM(p_ff2, g_ff2); GETSYM(p_fw1, g_fw1); GETSYM(p_fw2, g_fw2);
    GETSYM(p_ss, g_ss); GETSYM(p_x, g_x); GETSYM(p_part, g_part);

    auto conv = [](const float* s, bf16* d, int n) {
        k_convert<<<(n + 255) / 256, 256>>>(s, d, n);
    };

    conv(canvas,    p_canvas, CB * 384);
    conv(ce_w1,     p_cew1,   512 * 384);
    conv(ce_w2,     p_cew2,   256 * 512);
    conv(adaln1_w,  p_ad1,    CL * 512 * 256);
    conv(inproj_w,  p_inp,    CL * 768 * 256);
    conv(outproj_w, p_outp,   CL * 256 * 256);
    conv(adaln2_w,  p_ad2,    CL * 512 * 256);
    conv(ff1_w,     p_ff1,    CL * 1024 * 256);
    conv(ff2_w,     p_ff2,    CL * 256 * 1024);
    conv(fm_w2,     p_fw2,    512 * 512);
    k_convert_pad<<<(512 * 304 + 255) / 256, 256>>>(fm_w1, p_fw1);

    const int M = CB * CT;

    // context embedding: c = silu(canvas@ce_w1^T+b1) @ ce_w2^T + b2
    launch_gemm(1, p_canvas, p_cew1, ce_b1, p_t1, nullptr, CB, 512, 384);
    launch_gemm(0, p_t1,     p_cew2, ce_b2, p_cv, nullptr, CB, 256, 512);

    // stroke embedding -> fp32 residual stream
    k_semb<<<M, 256>>>(strokes, sp_w, sp_b, pos_emb, p_x);

    for (int l = 0; l < CL; l++) {
        // adaLN 1
        launch_gemm(3, p_cv, p_ad1 + (size_t)l * 512 * 256, adaln1_b + l * 512,
                    nullptr, p_ss, CB, 512, 256);
        k_mod<<<(M + 7) / 8, 256>>>(p_x, p_ss, p_x2);
        // qkv
        launch_gemm(0, p_x2, p_inp + (size_t)l * 768 * 256, inproj_b + l * 768,
                    p_qkv, nullptr, M, 768, 256);
        // attention (writes o into g_x2)
        k_attn<<<CB * 8, 128>>>(p_qkv, p_x2);
        // x += o @ outproj^T + b
        launch_gemm(2, p_x2, p_outp + (size_t)l * 256 * 256, outproj_b + l * 256,
                    nullptr, p_x, M, 256, 256);
        // adaLN 2
        launch_gemm(3, p_cv, p_ad2 + (size_t)l * 512 * 256, adaln2_b + l * 512,
                    nullptr, p_ss, CB, 512, 256);
        k_mod<<<(M + 7) / 8, 256>>>(p_x, p_ss, p_x2);
        // ff
        launch_gemm(1, p_x2, p_ff1 + (size_t)l * 1024 * 256, ff1_b + l * 1024,
                    p_ffh, nullptr, M, 1024, 256);
        launch_gemm(2, p_ffh, p_ff2 + (size_t)l * 256 * 1024, ff2_b + l * 256,
                    nullptr, p_x, M, 256, 1024);
    }

    // final LN + flow-matching head
    k_final<<<CB, 256>>>(p_x, on_g, on_b, a_tar, a_src, t_in, p_xin);
    launch_gemm(1, p_xin, p_fw1, fm_b1, p_t1, nullptr, CB, 512, 304);
    launch_gemm(1, p_t1,  p_fw2, fm_b2, p_t2, nullptr, CB, 512, 512);
    k_fm3<<<32, 256>>>(p_t2, fm_w3, fm_b3, a_tar, a_src, p_part);
    k_reduce<<<1, 32>>>(p_part, out);
}

// round 5
// speedup vs baseline: 1.2989x; 1.2989x over previous
#include <cuda_runtime.h>
#include <cuda_bf16.h>
#include <mma.h>
#include <cstdint>

using namespace nvcuda;
typedef __nv_bfloat16 bf16;

#define CB 8192
#define CT 30
#define CD 256
#define CL 6

// ---------------- scratch (static device arrays; no runtime alloc) ----------
__device__ bf16  g_canvas[CB*384];
__device__ bf16  g_t1[CB*512];
__device__ bf16  g_t2b[CB*512];
__device__ bf16  g_cv[CB*256];
__device__ float g_ssall[(size_t)CB*6144];   // all 12 adaLN outputs
__device__ float g_x[(size_t)CB*CT*CD];      // fp32 residual stream
__device__ bf16  g_x2[(size_t)CB*CT*CD];
__device__ bf16  g_qkv[(size_t)CB*CT*768];
__device__ bf16  g_ffh[(size_t)CB*CT*1024];
__device__ bf16  g_xin[CB*320];              // flow-matching input, K padded 296->320
__device__ float g_part[64];

__device__ bf16  g_ce_w1[512*384];
__device__ bf16  g_ce_w2[256*512];
__device__ bf16  g_adw[(size_t)6144*256];    // concat adaln1/adaln2 weights, all layers
__device__ float g_adb[6144];                // concat adaln biases
__device__ bf16  g_inp[CL*768*256];
__device__ bf16  g_outp[CL*256*256];
__device__ bf16  g_ff1[CL*1024*256];
__device__ bf16  g_ff2[CL*256*1024];
__device__ bf16  g_fw1[512*320];
__device__ bf16  g_fw2[512*512];

// ---------------- converts ----------------
__global__ void k_convert(const float* __restrict__ s, bf16* __restrict__ d, int n) {
    int i = blockIdx.x * 256 + threadIdx.x;
    if (i < n) d[i] = __float2bfloat16(s[i]);
}
__global__ void k_convert_pad(const float* __restrict__ s, bf16* __restrict__ d) {
    int i = blockIdx.x * 256 + threadIdx.x;
    if (i >= 512 * 320) return;
    int r = i / 320, k = i % 320;
    d[i] = (k < 296) ? __float2bfloat16(s[r * 296 + k]) : __float2bfloat16(0.f);
}
// concat adaln weights: row layout l*1024 + (which*512 + r)
__global__ void k_adw(const float* __restrict__ w1, const float* __restrict__ w2,
                      bf16* __restrict__ d) {
    int i = blockIdx.x * 256 + threadIdx.x;
    if (i >= 6144 * 256) return;
    int row = i >> 8, k = i & 255;
    int l = row >> 10, r = row & 1023;
    float v = (r < 512) ? w1[(size_t)l * 512 * 256 + r * 256 + k]
                        : w2[(size_t)l * 512 * 256 + (r - 512) * 256 + k];
    d[i] = __float2bfloat16(v);
}
__global__ void k_adb(const float* __restrict__ b1, const float* __restrict__ b2,
                      float* __restrict__ d) {
    int i = blockIdx.x * 256 + threadIdx.x;
    if (i >= 6144) return;
    int l = i >> 10, r = i & 1023;
    d[i] = (r < 512) ? b1[l * 512 + r] : b2[l * 512 + (r - 512)];
}

// ---------------- cp.async helpers ----------------
__device__ __forceinline__ void cp16(void* smem, const void* gmem) {
    uint32_t s = (uint32_t)__cvta_generic_to_shared(smem);
    asm volatile("cp.async.cg.shared.global [%0], [%1], 16;\n" :: "r"(s), "l"(gmem));
}
__device__ __forceinline__ void cp_commit() {
    asm volatile("cp.async.commit_group;\n");
}
template<int N>
__device__ __forceinline__ void cp_wait() {
    asm volatile("cp.async.wait_group %0;\n" :: "n"(N));
}

// ---------------- bf16 GEMM: C = A(MxK) @ W(NxK)^T + bias ------------------
// Requires: M%128==0, N%128==0, K%32==0. grid=(N/128, M/128), 256 threads.
// EPI: 0 bias->bf16 ; 1 bias+silu->bf16 ; 2 bias+residual add into fp32 ; 3 bias->fp32
template<int EPI>
__launch_bounds__(256)
__global__ void k_gemm(const bf16* __restrict__ A, const bf16* __restrict__ W,
                       const float* __restrict__ bias, bf16* __restrict__ outb,
                       float* __restrict__ outf, int M, int N, int K)
{
    __shared__ bf16 As[2][128 * 40];
    __shared__ bf16 Bs[2][128 * 40];

    const int tid  = threadIdx.x;
    const int wid  = tid >> 5;
    const int lane = tid & 31;
    const int n0   = blockIdx.x * 128;
    const int m0   = blockIdx.y * 128;
    const int wm   = (wid >> 2) * 64;   // 2 warp-rows
    const int wn   = (wid & 3) * 32;    // 4 warp-cols

    wmma::fragment<wmma::accumulator, 16, 16, 16, float> acc[4][2];
    #pragma unroll
    for (int i = 0; i < 4; i++)
        #pragma unroll
        for (int j = 0; j < 2; j++) wmma::fill_fragment(acc[i][j], 0.f);

    const int nk = K >> 5;

    auto load_stage = [&](int buf, int k0) {
        #pragma unroll
        for (int c = tid; c < 512; c += 256) {
            int row = c >> 2;
            int kc  = (c & 3) * 8;
            cp16(&As[buf][row * 40 + kc], A + (size_t)(m0 + row) * K + k0 + kc);
        }
        #pragma unroll
        for (int c = tid; c < 512; c += 256) {
            int row = c >> 2;
            int kc  = (c & 3) * 8;
            cp16(&Bs[buf][row * 40 + kc], W + (size_t)(n0 + row) * K + k0 + kc);
        }
        cp_commit();
    };

    load_stage(0, 0);

    for (int kt = 0; kt < nk; kt++) {
        if (kt + 1 < nk) {
            load_stage((kt + 1) & 1, (kt + 1) << 5);
            cp_wait<1>();
        } else {
            cp_wait<0>();
        }
        __syncthreads();
        int buf = kt & 1;
        #pragma unroll
        for (int kk = 0; kk < 32; kk += 16) {
            wmma::fragment<wmma::matrix_a, 16, 16, 16, bf16, wmma::row_major> af[4];
            wmma::fragment<wmma::matrix_b, 16, 16, 16, bf16, wmma::col_major> bfb[2];
            #pragma unroll
            for (int i = 0; i < 4; i++)
                wmma::load_matrix_sync(af[i], &As[buf][(wm + i * 16) * 40 + kk], 40);
            #pragma unroll
            for (int j = 0; j < 2; j++)
                wmma::load_matrix_sync(bfb[j], &Bs[buf][(wn + j * 16) * 40 + kk], 40);
            #pragma unroll
            for (int i = 0; i < 4; i++)
                #pragma unroll
                for (int j = 0; j < 2; j++)
                    wmma::mma_sync(acc[i][j], af[i], bfb[j], acc[i][j]);
        }
        __syncthreads();
    }

    // epilogue: stage each 16x16 frag through smem (reuse As as float area)
    float* wtile = reinterpret_cast<float*>(As) + wid * 288;   // 16x18 floats
    #pragma unroll
    for (int i = 0; i < 4; i++) {
        #pragma unroll
        for (int j = 0; j < 2; j++) {
            wmma::store_matrix_sync(wtile, acc[i][j], 18, wmma::mem_row_major);
            __syncwarp();
            #pragma unroll
            for (int p = 0; p < 8; p++) {
                int e = p * 32 + lane;
                int r = e >> 4, cc = e & 15;
                int m = m0 + wm + i * 16 + r;
                int n = n0 + wn + j * 16 + cc;
                float v = wtile[r * 18 + cc] + bias[n];
                if (EPI == 1) v = v / (1.f + __expf(-v));
                if (EPI == 2)      outf[(size_t)m * N + n] += v;
                else if (EPI == 3) outf[(size_t)m * N + n]  = v;
                else               outb[(size_t)m * N + n]  = __float2bfloat16(v);
            }
            __syncwarp();
        }
    }
}

// ---------------- stroke embedding ----------------
__global__ void k_semb(const float* __restrict__ strokes, const float* __restrict__ sp_w,
                       const float* __restrict__ sp_b, const float* __restrict__ pos,
                       float* __restrict__ x)
{
    int row = blockIdx.x;
    int t = row % CT;
    __shared__ float st[8];
    if (threadIdx.x < 8) st[threadIdx.x] = strokes[(size_t)row * 8 + threadIdx.x];
    __syncthreads();
    int d = threadIdx.x;
    float acc = sp_b[d] + pos[t * CD + d];
    #pragma unroll
    for (int s = 0; s < 8; s++) acc += st[s] * sp_w[d * 8 + s];
    x[(size_t)row * CD + d] = acc;
}

// ---------------- adaLN modulate: x2 = (1+sc)*ln(x)+sh ----------------
__global__ void k_mod(const float* __restrict__ x, const float* __restrict__ ssall,
                      bf16* __restrict__ x2, int off)
{
    int row = blockIdx.x * 8 + (threadIdx.x >> 5);
    if (row >= CB * CT) return;
    int lane = threadIdx.x & 31;
    int b = row / CT;
    const float* xr = x + (size_t)row * CD;
    float vals[8], s = 0.f, s2 = 0.f;
    #pragma unroll
    for (int i = 0; i < 8; i++) {
        float v = xr[lane + i * 32];
        vals[i] = v; s += v; s2 += v * v;
    }
    #pragma unroll
    for (int sh = 16; sh; sh >>= 1) {
        s  += __shfl_xor_sync(0xffffffffu, s, sh);
        s2 += __shfl_xor_sync(0xffffffffu, s2, sh);
    }
    float mean = s * (1.f / 256.f);
    float var  = s2 * (1.f / 256.f) - mean * mean;
    float rinv = rsqrtf(var + 1e-5f);
    const float* ssb = ssall + (size_t)b * 6144 + off;
    #pragma unroll
    for (int i = 0; i < 8; i++) {
        int d = lane + i * 32;
        float xn = (vals[i] - mean) * rinv;
        x2[(size_t)row * CD + d] = __float2bfloat16((1.f + ssb[d]) * xn + ssb[256 + d]);
    }
}

// ---------------- attention: one CTA (128 thr) per (b,h) -------------------
__global__ void k_attn(const bf16* __restrict__ qkv, bf16* __restrict__ o)
{
    int bh = blockIdx.x;
    int b = bh >> 3, h = bh & 7;
    __shared__ float sq[CT][33], sk[CT][33], sv[CT][33], sp[CT][33];
    int tid = threadIdx.x;
    size_t base = (size_t)b * CT * 768 + h * 32;
    for (int idx = tid; idx < CT * 32; idx += 128) {
        int t = idx >> 5, d = idx & 31;
        size_t p = base + (size_t)t * 768 + d;
        sq[t][d] = __bfloat162float(qkv[p]);
        sk[t][d] = __bfloat162float(qkv[p + 256]);
        sv[t][d] = __bfloat162float(qkv[p + 512]);
    }
    __syncthreads();
    const float scale = 0.17677669529663687f;
    for (int idx = tid; idx < CT * CT; idx += 128) {
        int i = idx / CT, j = idx % CT;
        if (j <= i) {
            float s = 0.f;
            #pragma unroll
            for (int d = 0; d < 32; d++) s += sq[i][d] * sk[j][d];
            sp[i][j] = s * scale;
        }
    }
    __syncthreads();
    int lane = tid & 31, w = tid >> 5;
    for (int i = w; i < CT; i += 4) {
        float v = (lane <= i) ? sp[i][lane] : -1e30f;
        float mx = v;
        #pragma unroll
        for (int s = 16; s; s >>= 1) mx = fmaxf(mx, __shfl_xor_sync(0xffffffffu, mx, s));
        float e = (lane <= i) ? __expf(v - mx) : 0.f;
        float sum = e;
        #pragma unroll
        for (int s = 16; s; s >>= 1) sum += __shfl_xor_sync(0xffffffffu, sum, s);
        if (lane <= i) sp[i][lane] = e / sum;
    }
    __syncthreads();
    for (int idx = tid; idx < CT * 32; idx += 128) {
        int i = idx >> 5, d = idx & 31;
        float s = 0.f;
        for (int j = 0; j <= i; j++) s += sp[i][j] * sv[j][d];
        o[(size_t)(b * CT + i) * CD + h * 32 + d] = __float2bfloat16(s);
    }
}

// ---------------- final LN + build flow-matching input ---------------------
__global__ void k_final(const float* __restrict__ x, const float* __restrict__ on_g,
                        const float* __restrict__ on_b, const float* __restrict__ a_tar,
                        const float* __restrict__ a_src, const float* __restrict__ t,
                        bf16* __restrict__ xin)
{
    int b = blockIdx.x;
    const float* xr = x + ((size_t)b * CT + 29) * CD;
    __shared__ float rbuf[2][8];
    __shared__ float stats[2];
    int tid = threadIdx.x;
    float v = xr[tid];
    float s = v, s2 = v * v;
    #pragma unroll
    for (int sh = 16; sh; sh >>= 1) {
        s  += __shfl_xor_sync(0xffffffffu, s, sh);
        s2 += __shfl_xor_sync(0xffffffffu, s2, sh);
    }
    if ((tid & 31) == 0) { rbuf[0][tid >> 5] = s; rbuf[1][tid >> 5] = s2; }
    __syncthreads();
    if (tid == 0) {
        float a = 0.f, q = 0.f;
        #pragma unroll
        for (int i = 0; i < 8; i++) { a += rbuf[0][i]; q += rbuf[1][i]; }
        float mean = a * (1.f / 256.f);
        float var  = q * (1.f / 256.f) - mean * mean;
        stats[0] = mean;
        stats[1] = rsqrtf(var + 1e-5f);
    }
    __syncthreads();
    float hn = (v - stats[0]) * stats[1] * on_g[tid] + on_b[tid];
    xin[(size_t)b * 320 + tid] = __float2bfloat16(hn);
    if (tid < 64) {
        int c = 256 + tid;
        float tv = t[b];
        float ov = 0.f;
        if (c < 264) {
            int i = c - 256;
            ov = (1.f - tv) * a_src[b * 8 + i] + tv * a_tar[b * 8 + i];
        } else if (c < 296) {
            int i = c - 264;
            int j = (i < 16) ? i : i - 16;
            float f = __expf(-9.210340371976184f * (float)j / 15.f);
            float a = tv * f;
            ov = (i < 16) ? sinf(a) : cosf(a);
        }
        xin[(size_t)b * 320 + c] = __float2bfloat16(ov);
    }
}

// ---------------- fm3 + loss partials --------------------------------------
__global__ void k_fm3(const bf16* __restrict__ t2, const float* __restrict__ w3,
                      const float* __restrict__ b3, const float* __restrict__ a_tar,
                      const float* __restrict__ a_src, float* __restrict__ part)
{
    __shared__ float sw3[8 * 512];
    int tid = threadIdx.x;
    for (int i = tid; i < 8 * 512; i += 256) sw3[i] = w3[i];
    __syncthreads();
    int b = blockIdx.x * 256 + tid;
    float acc[8];
    #pragma unroll
    for (int o = 0; o < 8; o++) acc[o] = b3[o];
    const bf16* tr = t2 + (size_t)b * 512;
    for (int k = 0; k < 512; k++) {
        float tv = __bfloat162float(tr[k]);
        #pragma unroll
        for (int o = 0; o < 8; o++) acc[o] += tv * sw3[o * 512 + k];
    }
    float local = 0.f;
    #pragma unroll
    for (int o = 0; o < 8; o++) {
        float u = a_tar[b * 8 + o] - a_src[b * 8 + o];
        float d = acc[o] - u;
        local += d * d;
    }
    local *= (1.f / 65536.f);
    #pragma unroll
    for (int sh = 16; sh; sh >>= 1) local += __shfl_xor_sync(0xffffffffu, local, sh);
    __shared__ float rb[8];
    if ((tid & 31) == 0) rb[tid >> 5] = local;
    __syncthreads();
    if (tid == 0) {
        float s = 0.f;
        #pragma unroll
        for (int i = 0; i < 8; i++) s += rb[i];
        part[blockIdx.x] = s;
    }
}

__global__ void k_reduce(const float* __restrict__ part, float* __restrict__ out)
{
    float s = part[threadIdx.x];
    #pragma unroll
    for (int sh = 16; sh; sh >>= 1) s += __shfl_xor_sync(0xffffffffu, s, sh);
    if (threadIdx.x == 0) out[0] = s;
}

// ---------------- host side ------------------------------------------------
static void launch_gemm(int epi, const bf16* A, const bf16* W, const float* bias,
                        bf16* ob, float* of, int M, int N, int K)
{
    dim3 g(N / 128, M / 128);
    switch (epi) {
        case 0: k_gemm<0><<<g, 256>>>(A, W, bias, ob, of, M, N, K); break;
        case 1: k_gemm<1><<<g, 256>>>(A, W, bias, ob, of, M, N, K); break;
        case 2: k_gemm<2><<<g, 256>>>(A, W, bias, ob, of, M, N, K); break;
        default: k_gemm<3><<<g, 256>>>(A, W, bias, ob, of, M, N, K); break;
    }
}

#define GETSYM(var, sym) do { void* _p; cudaGetSymbolAddress(&_p, sym); var = (decltype(var))_p; } while (0)

extern "C" void kernel_launch(void* const* d_in, const int* in_sizes, int n_in,
                              void* d_out, int out_size)
{
    const float* strokes    = (const float*)d_in[0];
    const float* canvas     = (const float*)d_in[1];
    const float* a_tar      = (const float*)d_in[2];
    const float* a_src      = (const float*)d_in[3];
    const float* t_in       = (const float*)d_in[4];
    const float* ce_w1      = (const float*)d_in[5];
    const float* ce_b1      = (const float*)d_in[6];
    const float* ce_w2      = (const float*)d_in[7];
    const float* ce_b2      = (const float*)d_in[8];
    const float* sp_w       = (const float*)d_in[9];
    const float* sp_b       = (const float*)d_in[10];
    const float* pos_emb    = (const float*)d_in[11];
    const float* adaln1_w   = (const float*)d_in[12];
    const float* adaln1_b   = (const float*)d_in[13];
    const float* inproj_w   = (const float*)d_in[14];
    const float* inproj_b   = (const float*)d_in[15];
    const float* outproj_w  = (const float*)d_in[16];
    const float* outproj_b  = (const float*)d_in[17];
    const float* adaln2_w   = (const float*)d_in[18];
    const float* adaln2_b   = (const float*)d_in[19];
    const float* ff1_w      = (const float*)d_in[20];
    const float* ff1_b      = (const float*)d_in[21];
    const float* ff2_w      = (const float*)d_in[22];
    const float* ff2_b      = (const float*)d_in[23];
    const float* on_g       = (const float*)d_in[24];
    const float* on_b       = (const float*)d_in[25];
    const float* fm_w1      = (const float*)d_in[26];
    const float* fm_b1      = (const float*)d_in[27];
    const float* fm_w2      = (const float*)d_in[28];
    const float* fm_b2      = (const float*)d_in[29];
    const float* fm_w3      = (const float*)d_in[30];
    const float* fm_b3      = (const float*)d_in[31];
    float* out = (float*)d_out;
    (void)in_sizes; (void)n_in; (void)out_size;

    bf16 *p_canvas, *p_t1, *p_t2, *p_cv, *p_x2, *p_qkv, *p_ffh, *p_xin;
    bf16 *p_cew1, *p_cew2, *p_adw, *p_inp, *p_outp, *p_ff1, *p_ff2, *p_fw1, *p_fw2;
    float *p_ssall, *p_adb, *p_x, *p_part;
    GETSYM(p_canvas, g_canvas); GETSYM(p_t1, g_t1); GETSYM(p_t2, g_t2b);
    GETSYM(p_cv, g_cv); GETSYM(p_x2, g_x2); GETSYM(p_qkv, g_qkv);
    GETSYM(p_ffh, g_ffh); GETSYM(p_xin, g_xin);
    GETSYM(p_cew1, g_ce_w1); GETSYM(p_cew2, g_ce_w2);
    GETSYM(p_adw, g_adw); GETSYM(p_adb, g_adb);
    GETSYM(p_inp, g_inp); GETSYM(p_outp, g_outp);
    GETSYM(p_ff1, g_ff1); GETSYM(p_ff2, g_ff2); GETSYM(p_fw1, g_fw1); GETSYM(p_fw2, g_fw2);
    GETSYM(p_ssall, g_ssall); GETSYM(p_x, g_x); GETSYM(p_part, g_part);

    auto conv = [](const float* s, bf16* d, int n) {
        k_convert<<<(n + 255) / 256, 256>>>(s, d, n);
    };

    conv(canvas,    p_canvas, CB * 384);
    conv(ce_w1,     p_cew1,   512 * 384);
    conv(ce_w2,     p_cew2,   256 * 512);
    conv(inproj_w,  p_inp,    CL * 768 * 256);
    conv(outproj_w, p_outp,   CL * 256 * 256);
    conv(ff1_w,     p_ff1,    CL * 1024 * 256);
    conv(ff2_w,     p_ff2,    CL * 256 * 1024);
    conv(fm_w2,     p_fw2,    512 * 512);
    k_convert_pad<<<(512 * 320 + 255) / 256, 256>>>(fm_w1, p_fw1);
    k_adw<<<(6144 * 256 + 255) / 256, 256>>>(adaln1_w, adaln2_w, p_adw);
    k_adb<<<(6144 + 255) / 256, 256>>>(adaln1_b, adaln2_b, p_adb);

    const int M = CB * CT;

    // context embedding: c = silu(canvas@ce_w1^T+b1) @ ce_w2^T + b2
    launch_gemm(1, p_canvas, p_cew1, ce_b1, p_t1, nullptr, CB, 512, 384);
    launch_gemm(0, p_t1,     p_cew2, ce_b2, p_cv, nullptr, CB, 256, 512);

    // ALL adaLN scale/shift for all layers in one GEMM (depends only on c)
    launch_gemm(3, p_cv, p_adw, p_adb, nullptr, p_ssall, CB, 6144, 256);

    // stroke embedding -> fp32 residual stream
    k_semb<<<M, 256>>>(strokes, sp_w, sp_b, pos_emb, p_x);

    for (int l = 0; l < CL; l++) {
        k_mod<<<(M + 7) / 8, 256>>>(p_x, p_ssall, p_x2, l * 1024);
        launch_gemm(0, p_x2, p_inp + (size_t)l * 768 * 256, inproj_b + l * 768,
                    p_qkv, nullptr, M, 768, 256);
        k_attn<<<CB * 8, 128>>>(p_qkv, p_x2);
        launch_gemm(2, p_x2, p_outp + (size_t)l * 256 * 256, outproj_b + l * 256,
                    nullptr, p_x, M, 256, 256);
        k_mod<<<(M + 7) / 8, 256>>>(p_x, p_ssall, p_x2, l * 1024 + 512);
        launch_gemm(1, p_x2, p_ff1 + (size_t)l * 1024 * 256, ff1_b + l * 1024,
                    p_ffh, nullptr, M, 1024, 256);
        launch_gemm(2, p_ffh, p_ff2 + (size_t)l * 256 * 1024, ff2_b + l * 256,
                    nullptr, p_x, M, 256, 1024);
    }

    // final LN + flow-matching head
    k_final<<<CB, 256>>>(p_x, on_g, on_b, a_tar, a_src, t_in, p_xin);
    launch_gemm(1, p_xin, p_fw1, fm_b1, p_t1, nullptr, CB, 512, 320);
    launch_gemm(1, p_t1,  p_fw2, fm_b2, p_t2, nullptr, CB, 512, 512);
    k_fm3<<<32, 256>>>(p_t2, fm_w3, fm_b3, a_tar, a_src, p_part);
    k_reduce<<<1, 32>>>(p_part, out);
}

// round 8
// speedup vs baseline: 1.8057x; 1.3903x over previous
#include <cuda_runtime.h>
#include <cuda_bf16.h>
#include <cstdint>

typedef __nv_bfloat16 bf16;

#define CB 8192
#define CT 30
#define CD 256
#define CL 6

// ---------------- scratch (static device arrays; no runtime alloc) ----------
__device__ bf16  g_canvas[CB*384];
__device__ bf16  g_t1[CB*512];
__device__ bf16  g_t2b[CB*512];
__device__ bf16  g_cv[CB*256];
__device__ float g_ssall[(size_t)CB*6144];
__device__ float g_x[(size_t)CB*CT*CD];
__device__ bf16  g_x2[(size_t)CB*CT*CD];
__device__ bf16  g_qkv[(size_t)CB*CT*768];
__device__ bf16  g_ffh[(size_t)CB*CT*1024];
__device__ bf16  g_xin[CB*320];
__device__ float g_part[64];

__device__ bf16  g_ce_w1[512*384];
__device__ bf16  g_ce_w2[256*512];
__device__ bf16  g_adw[(size_t)6144*256];
__device__ float g_adb[6144];
__device__ bf16  g_inp[CL*768*256];
__device__ bf16  g_outp[CL*256*256];
__device__ bf16  g_ff1[CL*1024*256];
__device__ bf16  g_ff2[CL*256*1024];
__device__ bf16  g_fw1[512*320];
__device__ bf16  g_fw2[512*512];

// ---------------- asm helpers ----------------
__device__ __forceinline__ void cp16(void* smem, const void* gmem) {
    uint32_t s = (uint32_t)__cvta_generic_to_shared(smem);
    asm volatile("cp.async.cg.shared.global [%0], [%1], 16;\n" :: "r"(s), "l"(gmem));
}
__device__ __forceinline__ void cp_commit() { asm volatile("cp.async.commit_group;\n"); }
template<int N> __device__ __forceinline__ void cp_wait() {
    asm volatile("cp.async.wait_group %0;\n" :: "n"(N));
}
__device__ __forceinline__ void ldsm4(uint32_t& r0, uint32_t& r1, uint32_t& r2, uint32_t& r3,
                                      uint32_t addr) {
    asm volatile("ldmatrix.sync.aligned.m8n8.x4.shared.b16 {%0,%1,%2,%3}, [%4];"
                 : "=r"(r0), "=r"(r1), "=r"(r2), "=r"(r3) : "r"(addr));
}
__device__ __forceinline__ void mma16816(float* d, const uint32_t* a, const uint32_t* b) {
    asm volatile("mma.sync.aligned.m16n8k16.row.col.f32.bf16.bf16.f32 "
                 "{%0,%1,%2,%3}, {%4,%5,%6,%7}, {%8,%9}, {%0,%1,%2,%3};"
                 : "+f"(d[0]), "+f"(d[1]), "+f"(d[2]), "+f"(d[3])
                 : "r"(a[0]), "r"(a[1]), "r"(a[2]), "r"(a[3]), "r"(b[0]), "r"(b[1]));
}

// ---------------- mma.sync GEMM: C = A(MxK) @ W(NxK)^T + bias --------------
// Requires M%128==0, N%128==0, K%64==0. grid=(N/128, M/128), 256 threads.
// EPI: 0 bias->bf16 ; 1 bias+silu->bf16 ; 2 bias+residual into fp32 ; 3 bias->fp32
// SMEM: 3 stages x (A 16KB + B 16KB). 128B rows, XOR-16B-granule swizzle.
#define GEMM_SMEM (3 * 32768)

template<int EPI>
__global__ void __launch_bounds__(256)
k_gemm(const bf16* __restrict__ A, const bf16* __restrict__ W,
       const float* __restrict__ bias, bf16* __restrict__ outb,
       float* __restrict__ outf, int M, int N, int K)
{
    extern __shared__ __align__(128) char smem[];
    const uint32_t sbase = (uint32_t)__cvta_generic_to_shared(smem);
    const int tid  = threadIdx.x;
    const int wid  = tid >> 5;
    const int lane = tid & 31;
    const int n0   = blockIdx.x * 128;
    const int m0   = blockIdx.y * 128;
    const int wm   = (wid >> 2) * 64;   // 2 warp-rows (m)
    const int wn   = (wid & 3) * 32;    // 4 warp-cols (n)

    float acc[4][4][4];
    #pragma unroll
    for (int i = 0; i < 4; i++)
        #pragma unroll
        for (int j = 0; j < 4; j++)
            #pragma unroll
            for (int e = 0; e < 4; e++) acc[i][j][e] = 0.f;

    const int nk = K >> 6;

    auto stage_load = [&](int kt) {
        char* sA = smem + (kt % 3) * 32768;
        char* sB = sA + 16384;
        const bf16* gA = A + (size_t)m0 * K + kt * 64;
        const bf16* gB = W + (size_t)n0 * K + kt * 64;
        #pragma unroll
        for (int i = tid; i < 1024; i += 256) {
            int row = i >> 3, g = i & 7;
            cp16(sA + row * 128 + 16 * (g ^ (row & 7)), gA + (size_t)row * K + g * 8);
        }
        #pragma unroll
        for (int i = tid; i < 1024; i += 256) {
            int row = i >> 3, g = i & 7;
            cp16(sB + row * 128 + 16 * (g ^ (row & 7)), gB + (size_t)row * K + g * 8);
        }
        cp_commit();
    };

    stage_load(0);
    if (nk > 1) stage_load(1);

    const int aRow = (lane & 7) + (((lane >> 3) & 1) << 3);  // ldmatrix A row map
    const int bRow = (lane & 7) + (((lane >> 4) & 1) << 3);  // ldmatrix B row map
    const int l7   = lane & 7;

    for (int kt = 0; kt < nk; kt++) {
        if (kt < nk - 1) cp_wait<1>(); else cp_wait<0>();
        __syncthreads();
        if (kt + 2 < nk) stage_load(kt + 2);

        uint32_t sA = sbase + (uint32_t)(kt % 3) * 32768;
        uint32_t sB = sA + 16384;
        #pragma unroll
        for (int ks = 0; ks < 4; ks++) {
            uint32_t a[4][4], b[4][2];
            int ca = (ks * 2 + (lane >> 4)) ^ l7;
            int cb = (ks * 2 + ((lane >> 3) & 1)) ^ l7;
            #pragma unroll
            for (int i = 0; i < 4; i++)
                ldsm4(a[i][0], a[i][1], a[i][2], a[i][3],
                      sA + (uint32_t)(wm + i * 16 + aRow) * 128 + ca * 16);
            #pragma unroll
            for (int j2 = 0; j2 < 2; j2++)
                ldsm4(b[j2 * 2][0], b[j2 * 2][1], b[j2 * 2 + 1][0], b[j2 * 2 + 1][1],
                      sB + (uint32_t)(wn + j2 * 16 + bRow) * 128 + cb * 16);
            #pragma unroll
            for (int i = 0; i < 4; i++)
                #pragma unroll
                for (int j = 0; j < 4; j++)
                    mma16816(acc[i][j], a[i], b[j]);
        }
    }

    // direct epilogue from accumulator fragments
    const int r = lane >> 2;
    const int c = (lane & 3) * 2;
    #pragma unroll
    for (int i = 0; i < 4; i++) {
        #pragma unroll
        for (int j = 0; j < 4; j++) {
            #pragma unroll
            for (int h = 0; h < 2; h++) {
                int m  = m0 + wm + i * 16 + r + h * 8;
                int nn = n0 + wn + j * 8 + c;
                float v0 = acc[i][j][h * 2 + 0] + bias[nn];
                float v1 = acc[i][j][h * 2 + 1] + bias[nn + 1];
                if (EPI == 1) {
                    v0 = v0 / (1.f + __expf(-v0));
                    v1 = v1 / (1.f + __expf(-v1));
                }
                if (EPI == 2) {
                    float2* p = (float2*)(outf + (size_t)m * N + nn);
                    float2 o = *p;
                    o.x += v0; o.y += v1;
                    *p = o;
                } else if (EPI == 3) {
                    float2* p = (float2*)(outf + (size_t)m * N + nn);
                    *p = make_float2(v0, v1);
                } else {
                    __nv_bfloat162* p = (__nv_bfloat162*)(outb + (size_t)m * N + nn);
                    *p = __nv_bfloat162(__float2bfloat16(v0), __float2bfloat16(v1));
                }
            }
        }
    }
}

// ---------------- converts ----------------
__global__ void k_convert(const float* __restrict__ s, bf16* __restrict__ d, int n) {
    int i = blockIdx.x * 256 + threadIdx.x;
    if (i < n) d[i] = __float2bfloat16(s[i]);
}
__global__ void k_convert_pad(const float* __restrict__ s, bf16* __restrict__ d) {
    int i = blockIdx.x * 256 + threadIdx.x;
    if (i >= 512 * 320) return;
    int r = i / 320, k = i % 320;
    d[i] = (k < 296) ? __float2bfloat16(s[r * 296 + k]) : __float2bfloat16(0.f);
}
__global__ void k_adw(const float* __restrict__ w1, const float* __restrict__ w2,
                      bf16* __restrict__ d) {
    int i = blockIdx.x * 256 + threadIdx.x;
    if (i >= 6144 * 256) return;
    int row = i >> 8, k = i & 255;
    int l = row >> 10, r = row & 1023;
    float v = (r < 512) ? w1[(size_t)l * 512 * 256 + r * 256 + k]
                        : w2[(size_t)l * 512 * 256 + (r - 512) * 256 + k];
    d[i] = __float2bfloat16(v);
}
__global__ void k_adb(const float* __restrict__ b1, const float* __restrict__ b2,
                      float* __restrict__ d) {
    int i = blockIdx.x * 256 + threadIdx.x;
    if (i >= 6144) return;
    int l = i >> 10, r = i & 1023;
    d[i] = (r < 512) ? b1[l * 512 + r] : b2[l * 512 + (r - 512)];
}

// ---------------- stroke embedding ----------------
__global__ void k_semb(const float* __restrict__ strokes, const float* __restrict__ sp_w,
                       const float* __restrict__ sp_b, const float* __restrict__ pos,
                       float* __restrict__ x)
{
    int row = blockIdx.x;
    int t = row % CT;
    __shared__ float st[8];
    if (threadIdx.x < 8) st[threadIdx.x] = strokes[(size_t)row * 8 + threadIdx.x];
    __syncthreads();
    int d = threadIdx.x;
    float acc = sp_b[d] + pos[t * CD + d];
    #pragma unroll
    for (int s = 0; s < 8; s++) acc += st[s] * sp_w[d * 8 + s];
    x[(size_t)row * CD + d] = acc;
}

// ---------------- adaLN modulate ----------------
__global__ void k_mod(const float* __restrict__ x, const float* __restrict__ ssall,
                      bf16* __restrict__ x2, int off)
{
    int row = blockIdx.x * 8 + (threadIdx.x >> 5);
    if (row >= CB * CT) return;
    int lane = threadIdx.x & 31;
    int b = row / CT;
    const float* xr = x + (size_t)row * CD;
    float vals[8], s = 0.f, s2 = 0.f;
    #pragma unroll
    for (int i = 0; i < 8; i++) {
        float v = xr[lane + i * 32];
        vals[i] = v; s += v; s2 += v * v;
    }
    #pragma unroll
    for (int sh = 16; sh; sh >>= 1) {
        s  += __shfl_xor_sync(0xffffffffu, s, sh);
        s2 += __shfl_xor_sync(0xffffffffu, s2, sh);
    }
    float mean = s * (1.f / 256.f);
    float var  = s2 * (1.f / 256.f) - mean * mean;
    float rinv = rsqrtf(var + 1e-5f);
    const float* ssb = ssall + (size_t)b * 6144 + off;
    #pragma unroll
    for (int i = 0; i < 8; i++) {
        int d = lane + i * 32;
        float xn = (vals[i] - mean) * rinv;
        x2[(size_t)row * CD + d] = __float2bfloat16((1.f + ssb[d]) * xn + ssb[256 + d]);
    }
}

// ---------------- attention ----------------
__global__ void k_attn(const bf16* __restrict__ qkv, bf16* __restrict__ o)
{
    int bh = blockIdx.x;
    int b = bh >> 3, h = bh & 7;
    __shared__ float sq[CT][33], sk[CT][33], sv[CT][33], sp[CT][33];
    int tid = threadIdx.x;
    size_t base = (size_t)b * CT * 768 + h * 32;
    for (int idx = tid; idx < CT * 32; idx += 128) {
        int t = idx >> 5, d = idx & 31;
        size_t p = base + (size_t)t * 768 + d;
        sq[t][d] = __bfloat162float(qkv[p]);
        sk[t][d] = __bfloat162float(qkv[p + 256]);
        sv[t][d] = __bfloat162float(qkv[p + 512]);
    }
    __syncthreads();
    const float scale = 0.17677669529663687f;
    for (int idx = tid; idx < CT * CT; idx += 128) {
        int i = idx / CT, j = idx % CT;
        if (j <= i) {
            float s = 0.f;
            #pragma unroll
            for (int d = 0; d < 32; d++) s += sq[i][d] * sk[j][d];
            sp[i][j] = s * scale;
        }
    }
    __syncthreads();
    int lane = tid & 31, w = tid >> 5;
    for (int i = w; i < CT; i += 4) {
        float v = (lane <= i) ? sp[i][lane] : -1e30f;
        float mx = v;
        #pragma unroll
        for (int s = 16; s; s >>= 1) mx = fmaxf(mx, __shfl_xor_sync(0xffffffffu, mx, s));
        float e = (lane <= i) ? __expf(v - mx) : 0.f;
        float sum = e;
        #pragma unroll
        for (int s = 16; s; s >>= 1) sum += __shfl_xor_sync(0xffffffffu, sum, s);
        if (lane <= i) sp[i][lane] = e / sum;
    }
    __syncthreads();
    for (int idx = tid; idx < CT * 32; idx += 128) {
        int i = idx >> 5, d = idx & 31;
        float s = 0.f;
        for (int j = 0; j <= i; j++) s += sp[i][j] * sv[j][d];
        o[(size_t)(b * CT + i) * CD + h * 32 + d] = __float2bfloat16(s);
    }
}

// ---------------- final LN + flow-matching input ----------------
__global__ void k_final(const float* __restrict__ x, const float* __restrict__ on_g,
                        const float* __restrict__ on_b, const float* __restrict__ a_tar,
                        const float* __restrict__ a_src, const float* __restrict__ t,
                        bf16* __restrict__ xin)
{
    int b = blockIdx.x;
    const float* xr = x + ((size_t)b * CT + 29) * CD;
    __shared__ float rbuf[2][8];
    __shared__ float stats[2];
    int tid = threadIdx.x;
    float v = xr[tid];
    float s = v, s2 = v * v;
    #pragma unroll
    for (int sh = 16; sh; sh >>= 1) {
        s  += __shfl_xor_sync(0xffffffffu, s, sh);
        s2 += __shfl_xor_sync(0xffffffffu, s2, sh);
    }
    if ((tid & 31) == 0) { rbuf[0][tid >> 5] = s; rbuf[1][tid >> 5] = s2; }
    __syncthreads();
    if (tid == 0) {
        float a = 0.f, q = 0.f;
        #pragma unroll
        for (int i = 0; i < 8; i++) { a += rbuf[0][i]; q += rbuf[1][i]; }
        float mean = a * (1.f / 256.f);
        float var  = q * (1.f / 256.f) - mean * mean;
        stats[0] = mean;
        stats[1] = rsqrtf(var + 1e-5f);
    }
    __syncthreads();
    float hn = (v - stats[0]) * stats[1] * on_g[tid] + on_b[tid];
    xin[(size_t)b * 320 + tid] = __float2bfloat16(hn);
    if (tid < 64) {
        int c = 256 + tid;
        float tv = t[b];
        float ov = 0.f;
        if (c < 264) {
            int i = c - 256;
            ov = (1.f - tv) * a_src[b * 8 + i] + tv * a_tar[b * 8 + i];
        } else if (c < 296) {
            int i = c - 264;
            int j = (i < 16) ? i : i - 16;
            float f = __expf(-9.210340371976184f * (float)j / 15.f);
            float a = tv * f;
            ov = (i < 16) ? sinf(a) : cosf(a);
        }
        xin[(size_t)b * 320 + c] = __float2bfloat16(ov);
    }
}

// ---------------- fm3 + loss ----------------
__global__ void k_fm3(const bf16* __restrict__ t2, const float* __restrict__ w3,
                      const float* __restrict__ b3, const float* __restrict__ a_tar,
                      const float* __restrict__ a_src, float* __restrict__ part)
{
    __shared__ float sw3[8 * 512];
    int tid = threadIdx.x;
    for (int i = tid; i < 8 * 512; i += 256) sw3[i] = w3[i];
    __syncthreads();
    int b = blockIdx.x * 256 + tid;
    float acc[8];
    #pragma unroll
    for (int o = 0; o < 8; o++) acc[o] = b3[o];
    const bf16* tr = t2 + (size_t)b * 512;
    for (int k = 0; k < 512; k++) {
        float tv = __bfloat162float(tr[k]);
        #pragma unroll
        for (int o = 0; o < 8; o++) acc[o] += tv * sw3[o * 512 + k];
    }
    float local = 0.f;
    #pragma unroll
    for (int o = 0; o < 8; o++) {
        float u = a_tar[b * 8 + o] - a_src[b * 8 + o];
        float d = acc[o] - u;
        local += d * d;
    }
    local *= (1.f / 65536.f);
    #pragma unroll
    for (int sh = 16; sh; sh >>= 1) local += __shfl_xor_sync(0xffffffffu, local, sh);
    __shared__ float rb[8];
    if ((tid & 31) == 0) rb[tid >> 5] = local;
    __syncthreads();
    if (tid == 0) {
        float s = 0.f;
        #pragma unroll
        for (int i = 0; i < 8; i++) s += rb[i];
        part[blockIdx.x] = s;
    }
}

__global__ void k_reduce(const float* __restrict__ part, float* __restrict__ out)
{
    float s = part[threadIdx.x];
    #pragma unroll
    for (int sh = 16; sh; sh >>= 1) s += __shfl_xor_sync(0xffffffffu, s, sh);
    if (threadIdx.x == 0) out[0] = s;
}

// ---------------- host side ------------------------------------------------
static void launch_gemm(int epi, const bf16* A, const bf16* W, const float* bias,
                        bf16* ob, float* of, int M, int N, int K)
{
    dim3 g(N / 128, M / 128);
    switch (epi) {
        case 0: k_gemm<0><<<g, 256, GEMM_SMEM>>>(A, W, bias, ob, of, M, N, K); break;
        case 1: k_gemm<1><<<g, 256, GEMM_SMEM>>>(A, W, bias, ob, of, M, N, K); break;
        case 2: k_gemm<2><<<g, 256, GEMM_SMEM>>>(A, W, bias, ob, of, M, N, K); break;
        default: k_gemm<3><<<g, 256, GEMM_SMEM>>>(A, W, bias, ob, of, M, N, K); break;
    }
}

#define GETSYM(var, sym) do { void* _p; cudaGetSymbolAddress(&_p, sym); var = (decltype(var))_p; } while (0)

extern "C" void kernel_launch(void* const* d_in, const int* in_sizes, int n_in,
                              void* d_out, int out_size)
{
    const float* strokes    = (const float*)d_in[0];
    const float* canvas     = (const float*)d_in[1];
    const float* a_tar      = (const float*)d_in[2];
    const float* a_src      = (const float*)d_in[3];
    const float* t_in       = (const float*)d_in[4];
    const float* ce_w1      = (const float*)d_in[5];
    const float* ce_b1      = (const float*)d_in[6];
    const float* ce_w2      = (const float*)d_in[7];
    const float* ce_b2      = (const float*)d_in[8];
    const float* sp_w       = (const float*)d_in[9];
    const float* sp_b       = (const float*)d_in[10];
    const float* pos_emb    = (const float*)d_in[11];
    const float* adaln1_w   = (const float*)d_in[12];
    const float* adaln1_b   = (const float*)d_in[13];
    const float* inproj_w   = (const float*)d_in[14];
    const float* inproj_b   = (const float*)d_in[15];
    const float* outproj_w  = (const float*)d_in[16];
    const float* outproj_b  = (const float*)d_in[17];
    const float* adaln2_w   = (const float*)d_in[18];
    const float* adaln2_b   = (const float*)d_in[19];
    const float* ff1_w      = (const float*)d_in[20];
    const float* ff1_b      = (const float*)d_in[21];
    const float* ff2_w      = (const float*)d_in[22];
    const float* ff2_b      = (const float*)d_in[23];
    const float* on_g       = (const float*)d_in[24];
    const float* on_b       = (const float*)d_in[25];
    const float* fm_w1      = (const float*)d_in[26];
    const float* fm_b1      = (const float*)d_in[27];
    const float* fm_w2      = (const float*)d_in[28];
    const float* fm_b2      = (const float*)d_in[29];
    const float* fm_w3      = (const float*)d_in[30];
    const float* fm_b3      = (const float*)d_in[31];
    float* out = (float*)d_out;
    (void)in_sizes; (void)n_in; (void)out_size;

    static int attr_done = 0;
    if (!attr_done) {
        cudaFuncSetAttribute(k_gemm<0>, cudaFuncAttributeMaxDynamicSharedMemorySize, GEMM_SMEM);
        cudaFuncSetAttribute(k_gemm<1>, cudaFuncAttributeMaxDynamicSharedMemorySize, GEMM_SMEM);
        cudaFuncSetAttribute(k_gemm<2>, cudaFuncAttributeMaxDynamicSharedMemorySize, GEMM_SMEM);
        cudaFuncSetAttribute(k_gemm<3>, cudaFuncAttributeMaxDynamicSharedMemorySize, GEMM_SMEM);
        attr_done = 1;
    }

    bf16 *p_canvas, *p_t1, *p_t2, *p_cv, *p_x2, *p_qkv, *p_ffh, *p_xin;
    bf16 *p_cew1, *p_cew2, *p_adw, *p_inp, *p_outp, *p_ff1, *p_ff2, *p_fw1, *p_fw2;
    float *p_ssall, *p_adb, *p_x, *p_part;
    GETSYM(p_canvas, g_canvas); GETSYM(p_t1, g_t1); GETSYM(p_t2, g_t2b);
    GETSYM(p_cv, g_cv); GETSYM(p_x2, g_x2); GETSYM(p_qkv, g_qkv);
    GETSYM(p_ffh, g_ffh); GETSYM(p_xin, g_xin);
    GETSYM(p_cew1, g_ce_w1); GETSYM(p_cew2, g_ce_w2);
    GETSYM(p_adw, g_adw); GETSYM(p_adb, g_adb);
    GETSYM(p_inp, g_inp); GETSYM(p_outp, g_outp);
    GETSYM(p_ff1, g_ff1); GETSYM(p_ff2, g_ff2); GETSYM(p_fw1, g_fw1); GETSYM(p_fw2, g_fw2);
    GETSYM(p_ssall, g_ssall); GETSYM(p_x, g_x); GETSYM(p_part, g_part);

    auto conv = [](const float* s, bf16* d, int n) {
        k_convert<<<(n + 255) / 256, 256>>>(s, d, n);
    };

    conv(canvas,    p_canvas, CB * 384);
    conv(ce_w1,     p_cew1,   512 * 384);
    conv(ce_w2,     p_cew2,   256 * 512);
    conv(inproj_w,  p_inp,    CL * 768 * 256);
    conv(outproj_w, p_outp,   CL * 256 * 256);
    conv(ff1_w,     p_ff1,    CL * 1024 * 256);
    conv(ff2_w,     p_ff2,    CL * 256 * 1024);
    conv(fm_w2,     p_fw2,    512 * 512);
    k_convert_pad<<<(512 * 320 + 255) / 256, 256>>>(fm_w1, p_fw1);
    k_adw<<<(6144 * 256 + 255) / 256, 256>>>(adaln1_w, adaln2_w, p_adw);
    k_adb<<<(6144 + 255) / 256, 256>>>(adaln1_b, adaln2_b, p_adb);

    const int M = CB * CT;

    // context embedding
    launch_gemm(1, p_canvas, p_cew1, ce_b1, p_t1, nullptr, CB, 512, 384);
    launch_gemm(0, p_t1,     p_cew2, ce_b2, p_cv, nullptr, CB, 256, 512);

    // ALL adaLN scale/shift for all layers in one GEMM
    launch_gemm(3, p_cv, p_adw, p_adb, nullptr, p_ssall, CB, 6144, 256);

    // stroke embedding -> fp32 residual stream
    k_semb<<<M, 256>>>(strokes, sp_w, sp_b, pos_emb, p_x);

    for (int l = 0; l < CL; l++) {
        k_mod<<<(M + 7) / 8, 256>>>(p_x, p_ssall, p_x2, l * 1024);
        launch_gemm(0, p_x2, p_inp + (size_t)l * 768 * 256, inproj_b + l * 768,
                    p_qkv, nullptr, M, 768, 256);
        k_attn<<<CB * 8, 128>>>(p_qkv, p_x2);
        launch_gemm(2, p_x2, p_outp + (size_t)l * 256 * 256, outproj_b + l * 256,
                    nullptr, p_x, M, 256, 256);
        k_mod<<<(M + 7) / 8, 256>>>(p_x, p_ssall, p_x2, l * 1024 + 512);
        launch_gemm(1, p_x2, p_ff1 + (size_t)l * 1024 * 256, ff1_b + l * 1024,
                    p_ffh, nullptr, M, 1024, 256);
        launch_gemm(2, p_ffh, p_ff2 + (size_t)l * 256 * 1024, ff2_b + l * 256,
                    nullptr, p_x, M, 256, 1024);
    }

    // final LN + flow-matching head
    k_final<<<CB, 256>>>(p_x, on_g, on_b, a_tar, a_src, t_in, p_xin);
    launch_gemm(1, p_xin, p_fw1, fm_b1, p_t1, nullptr, CB, 512, 320);
    launch_gemm(1, p_t1,  p_fw2, fm_b2, p_t2, nullptr, CB, 512, 512);
    k_fm3<<<32, 256>>>(p_t2, fm_w3, fm_b3, a_tar, a_src, p_part);
    k_reduce<<<1, 32>>>(p_part, out);
}

// round 9
// speedup vs baseline: 1.8503x; 1.0246x over previous
#include <cuda_runtime.h>
#include <cuda_bf16.h>
#include <cstdint>

typedef __nv_bfloat16 bf16;

#define CB 8192
#define CT 30
#define CD 256
#define CL 6

// ---------------- scratch ----------------
__device__ bf16  g_canvas[CB*384];
__device__ bf16  g_t1[CB*512];
__device__ bf16  g_t2b[CB*512];
__device__ bf16  g_cv[CB*256];
__device__ float g_ssall[(size_t)CB*6144];
__device__ bf16  g_xb[(size_t)CB*CT*CD];     // bf16 residual stream
__device__ bf16  g_x2[(size_t)CB*CT*CD];
__device__ bf16  g_qkv[(size_t)CB*CT*768];
__device__ bf16  g_ffh[(size_t)CB*CT*1024];
__device__ bf16  g_xin[CB*320];
__device__ float g_part[64];

__device__ bf16  g_ce_w1[512*384];
__device__ bf16  g_ce_w2[256*512];
__device__ bf16  g_adw[(size_t)6144*256];
__device__ float g_adb[6144];
__device__ bf16  g_inp[CL*768*256];
__device__ bf16  g_outp[CL*256*256];
__device__ bf16  g_ff1[CL*1024*256];
__device__ bf16  g_ff2[CL*256*1024];
__device__ bf16  g_fw1[512*320];
__device__ bf16  g_fw2[512*512];

// ---------------- asm helpers ----------------
__device__ __forceinline__ void cp16(void* smem, const void* gmem) {
    uint32_t s = (uint32_t)__cvta_generic_to_shared(smem);
    asm volatile("cp.async.cg.shared.global [%0], [%1], 16;\n" :: "r"(s), "l"(gmem));
}
__device__ __forceinline__ void cp_commit() { asm volatile("cp.async.commit_group;\n"); }
template<int N> __device__ __forceinline__ void cp_wait() {
    asm volatile("cp.async.wait_group %0;\n" :: "n"(N));
}
__device__ __forceinline__ void ldsm4(uint32_t& r0, uint32_t& r1, uint32_t& r2, uint32_t& r3,
                                      uint32_t addr) {
    asm volatile("ldmatrix.sync.aligned.m8n8.x4.shared.b16 {%0,%1,%2,%3}, [%4];"
                 : "=r"(r0), "=r"(r1), "=r"(r2), "=r"(r3) : "r"(addr));
}
__device__ __forceinline__ void mma16816(float* d, const uint32_t* a, const uint32_t* b) {
    asm volatile("mma.sync.aligned.m16n8k16.row.col.f32.bf16.bf16.f32 "
                 "{%0,%1,%2,%3}, {%4,%5,%6,%7}, {%8,%9}, {%0,%1,%2,%3};"
                 : "+f"(d[0]), "+f"(d[1]), "+f"(d[2]), "+f"(d[3])
                 : "r"(a[0]), "r"(a[1]), "r"(a[2]), "r"(a[3]), "r"(b[0]), "r"(b[1]));
}

// ============ generic GEMM (BN=128): C = A @ W^T + bias =====================
// EPI: 0 bias->bf16 ; 1 bias+silu->bf16 ; 3 bias->fp32
#define GEMM_SMEM (3 * 32768)

template<int EPI>
__global__ void __launch_bounds__(256)
k_gemm(const bf16* __restrict__ A, const bf16* __restrict__ W,
       const float* __restrict__ bias, bf16* __restrict__ outb,
       float* __restrict__ outf, int M, int N, int K)
{
    extern __shared__ __align__(128) char smem[];
    const uint32_t sbase = (uint32_t)__cvta_generic_to_shared(smem);
    const int tid  = threadIdx.x;
    const int wid  = tid >> 5;
    const int lane = tid & 31;
    const int n0   = blockIdx.x * 128;
    const int m0   = blockIdx.y * 128;
    const int wm   = (wid >> 2) * 64;
    const int wn   = (wid & 3) * 32;

    float acc[4][4][4];
    #pragma unroll
    for (int i = 0; i < 4; i++)
        #pragma unroll
        for (int j = 0; j < 4; j++)
            #pragma unroll
            for (int e = 0; e < 4; e++) acc[i][j][e] = 0.f;

    const int nk = K >> 6;

    auto stage_load = [&](int kt) {
        char* sA = smem + (kt % 3) * 32768;
        char* sB = sA + 16384;
        const bf16* gA = A + (size_t)m0 * K + kt * 64;
        const bf16* gB = W + (size_t)n0 * K + kt * 64;
        #pragma unroll
        for (int i = tid; i < 1024; i += 256) {
            int row = i >> 3, g = i & 7;
            cp16(sA + row * 128 + 16 * (g ^ (row & 7)), gA + (size_t)row * K + g * 8);
        }
        #pragma unroll
        for (int i = tid; i < 1024; i += 256) {
            int row = i >> 3, g = i & 7;
            cp16(sB + row * 128 + 16 * (g ^ (row & 7)), gB + (size_t)row * K + g * 8);
        }
        cp_commit();
    };

    stage_load(0);
    if (nk > 1) stage_load(1);

    const int aRow = (lane & 7) + (((lane >> 3) & 1) << 3);
    const int bRow = (lane & 7) + (((lane >> 4) & 1) << 3);
    const int l7   = lane & 7;

    for (int kt = 0; kt < nk; kt++) {
        if (kt < nk - 1) cp_wait<1>(); else cp_wait<0>();
        __syncthreads();
        if (kt + 2 < nk) stage_load(kt + 2);

        uint32_t sA = sbase + (uint32_t)(kt % 3) * 32768;
        uint32_t sB = sA + 16384;
        #pragma unroll
        for (int ks = 0; ks < 4; ks++) {
            uint32_t a[4][4], b[4][2];
            int ca = (ks * 2 + (lane >> 4)) ^ l7;
            int cb = (ks * 2 + ((lane >> 3) & 1)) ^ l7;
            #pragma unroll
            for (int i = 0; i < 4; i++)
                ldsm4(a[i][0], a[i][1], a[i][2], a[i][3],
                      sA + (uint32_t)(wm + i * 16 + aRow) * 128 + ca * 16);
            #pragma unroll
            for (int j2 = 0; j2 < 2; j2++)
                ldsm4(b[j2 * 2][0], b[j2 * 2][1], b[j2 * 2 + 1][0], b[j2 * 2 + 1][1],
                      sB + (uint32_t)(wn + j2 * 16 + bRow) * 128 + cb * 16);
            #pragma unroll
            for (int i = 0; i < 4; i++)
                #pragma unroll
                for (int j = 0; j < 4; j++)
                    mma16816(acc[i][j], a[i], b[j]);
        }
    }

    const int r = lane >> 2;
    const int c = (lane & 3) * 2;
    #pragma unroll
    for (int i = 0; i < 4; i++) {
        #pragma unroll
        for (int j = 0; j < 4; j++) {
            #pragma unroll
            for (int h = 0; h < 2; h++) {
                int m  = m0 + wm + i * 16 + r + h * 8;
                int nn = n0 + wn + j * 8 + c;
                float v0 = acc[i][j][h * 2 + 0] + bias[nn];
                float v1 = acc[i][j][h * 2 + 1] + bias[nn + 1];
                if (EPI == 1) {
                    v0 = v0 / (1.f + __expf(-v0));
                    v1 = v1 / (1.f + __expf(-v1));
                }
                if (EPI == 3) {
                    *(float2*)(outf + (size_t)m * N + nn) = make_float2(v0, v1);
                } else {
                    *(__nv_bfloat162*)(outb + (size_t)m * N + nn) =
                        __nv_bfloat162(__float2bfloat16(v0), __float2bfloat16(v1));
                }
            }
        }
    }
}

// ============ fused residual GEMM (N=256): x += A@W^T + b; x2 = mod(ln(x)) ==
// BM=128, BN=256, BK=64, 512 threads (16 warps, 4m x 4n, warp tile 32x64).
// MOD=1: also write x2 = (1+sc)*ln(xnew)+sh using ssall[b*6144+off ...]
#define GEMMRM_SMEM (3 * 49152)

template<int MOD>
__global__ void __launch_bounds__(512)
k_gemm_rm(const bf16* __restrict__ A, const bf16* __restrict__ W,
          const float* __restrict__ bias, bf16* __restrict__ x,
          bf16* __restrict__ x2, const float* __restrict__ ssall,
          int off, int M, int K)
{
    extern __shared__ __align__(128) char smem[];
    const uint32_t sbase = (uint32_t)__cvta_generic_to_shared(smem);
    const int tid  = threadIdx.x;
    const int wid  = tid >> 5;
    const int lane = tid & 31;
    const int m0   = blockIdx.x * 128;
    const int wm   = (wid >> 2) * 32;
    const int wn   = (wid & 3) * 64;

    float acc[2][8][4];
    #pragma unroll
    for (int i = 0; i < 2; i++)
        #pragma unroll
        for (int j = 0; j < 8; j++)
            #pragma unroll
            for (int e = 0; e < 4; e++) acc[i][j][e] = 0.f;

    const int nk = K >> 6;

    auto stage_load = [&](int kt) {
        char* sA = smem + (kt % 3) * 49152;
        char* sB = sA + 16384;
        const bf16* gA = A + (size_t)m0 * K + kt * 64;
        const bf16* gB = W + (size_t)kt * 64;
        #pragma unroll
        for (int i = tid; i < 1024; i += 512) {
            int row = i >> 3, g = i & 7;
            cp16(sA + row * 128 + 16 * (g ^ (row & 7)), gA + (size_t)row * K + g * 8);
        }
        #pragma unroll
        for (int i = tid; i < 2048; i += 512) {
            int row = i >> 3, g = i & 7;
            cp16(sB + row * 128 + 16 * (g ^ (row & 7)), gB + (size_t)row * K + g * 8);
        }
        cp_commit();
    };

    stage_load(0);
    if (nk > 1) stage_load(1);

    const int aRow = (lane & 7) + (((lane >> 3) & 1) << 3);
    const int bRow = (lane & 7) + (((lane >> 4) & 1) << 3);
    const int l7   = lane & 7;

    for (int kt = 0; kt < nk; kt++) {
        if (kt < nk - 1) cp_wait<1>(); else cp_wait<0>();
        __syncthreads();
        if (kt + 2 < nk) stage_load(kt + 2);

        uint32_t sA = sbase + (uint32_t)(kt % 3) * 49152;
        uint32_t sB = sA + 16384;
        #pragma unroll
        for (int ks = 0; ks < 4; ks++) {
            uint32_t a[2][4], b[8][2];
            int ca = (ks * 2 + (lane >> 4)) ^ l7;
            int cb = (ks * 2 + ((lane >> 3) & 1)) ^ l7;
            #pragma unroll
            for (int i = 0; i < 2; i++)
                ldsm4(a[i][0], a[i][1], a[i][2], a[i][3],
                      sA + (uint32_t)(wm + i * 16 + aRow) * 128 + ca * 16);
            #pragma unroll
            for (int g = 0; g < 4; g++)
                ldsm4(b[g * 2][0], b[g * 2][1], b[g * 2 + 1][0], b[g * 2 + 1][1],
                      sB + (uint32_t)(wn + g * 16 + bRow) * 128 + cb * 16);
            #pragma unroll
            for (int i = 0; i < 2; i++)
                #pragma unroll
                for (int j = 0; j < 8; j++)
                    mma16816(acc[i][j], a[i], b[j]);
        }
    }

    // ---------------- fused epilogue ----------------
    __syncthreads();                       // everyone done reading smem tiles
    float* parts = (float*)smem;           // [128 rows][4 ngroups][2]
    const int r = lane >> 2;
    const int c = (lane & 3) * 2;

    // residual + bias, write xnew, accumulate row partials
    #pragma unroll
    for (int i = 0; i < 2; i++) {
        #pragma unroll
        for (int h = 0; h < 2; h++) {
            int ml = wm + i * 16 + r + h * 8;
            int m  = m0 + ml;
            float s = 0.f, q = 0.f;
            #pragma unroll
            for (int j = 0; j < 8; j++) {
                int nn = wn + j * 8 + c;
                __nv_bfloat162 xo = *(__nv_bfloat162*)(x + (size_t)m * 256 + nn);
                float v0 = acc[i][j][h * 2 + 0] + bias[nn]     + __bfloat162float(xo.x);
                float v1 = acc[i][j][h * 2 + 1] + bias[nn + 1] + __bfloat162float(xo.y);
                acc[i][j][h * 2 + 0] = v0;
                acc[i][j][h * 2 + 1] = v1;
                s += v0 + v1;
                q += v0 * v0 + v1 * v1;
                *(__nv_bfloat162*)(x + (size_t)m * 256 + nn) =
                    __nv_bfloat162(__float2bfloat16(v0), __float2bfloat16(v1));
            }
            if (MOD) {
                s += __shfl_xor_sync(0xffffffffu, s, 1);
                s += __shfl_xor_sync(0xffffffffu, s, 2);
                q += __shfl_xor_sync(0xffffffffu, q, 1);
                q += __shfl_xor_sync(0xffffffffu, q, 2);
                if ((lane & 3) == 0) {
                    parts[ml * 8 + (wid & 3) * 2 + 0] = s;
                    parts[ml * 8 + (wid & 3) * 2 + 1] = q;
                }
            }
        }
    }
    if (!MOD) return;
    __syncthreads();

    #pragma unroll
    for (int i = 0; i < 2; i++) {
        #pragma unroll
        for (int h = 0; h < 2; h++) {
            int ml = wm + i * 16 + r + h * 8;
            int m  = m0 + ml;
            float s = parts[ml * 8 + 0] + parts[ml * 8 + 2] + parts[ml * 8 + 4] + parts[ml * 8 + 6];
            float q = parts[ml * 8 + 1] + parts[ml * 8 + 3] + parts[ml * 8 + 5] + parts[ml * 8 + 7];
            float mean = s * (1.f / 256.f);
            float var  = q * (1.f / 256.f) - mean * mean;
            float rinv = rsqrtf(var + 1e-5f);
            const float* ssb = ssall + (size_t)(m / CT) * 6144 + off;
            #pragma unroll
            for (int j = 0; j < 8; j++) {
                int nn = wn + j * 8 + c;
                float xn0 = (acc[i][j][h * 2 + 0] - mean) * rinv;
                float xn1 = (acc[i][j][h * 2 + 1] - mean) * rinv;
                float o0 = (1.f + ssb[nn])     * xn0 + ssb[256 + nn];
                float o1 = (1.f + ssb[nn + 1]) * xn1 + ssb[256 + nn + 1];
                *(__nv_bfloat162*)(x2 + (size_t)m * 256 + nn) =
                    __nv_bfloat162(__float2bfloat16(o0), __float2bfloat16(o1));
            }
        }
    }
}

// ---------------- converts ----------------
__global__ void k_convert(const float* __restrict__ s, bf16* __restrict__ d, int n) {
    int i = blockIdx.x * 256 + threadIdx.x;
    if (i < n) d[i] = __float2bfloat16(s[i]);
}
__global__ void k_convert_pad(const float* __restrict__ s, bf16* __restrict__ d) {
    int i = blockIdx.x * 256 + threadIdx.x;
    if (i >= 512 * 320) return;
    int r = i / 320, k = i % 320;
    d[i] = (k < 296) ? __float2bfloat16(s[r * 296 + k]) : __float2bfloat16(0.f);
}
__global__ void k_adw(const float* __restrict__ w1, const float* __restrict__ w2,
                      bf16* __restrict__ d) {
    int i = blockIdx.x * 256 + threadIdx.x;
    if (i >= 6144 * 256) return;
    int row = i >> 8, k = i & 255;
    int l = row >> 10, r = row & 1023;
    float v = (r < 512) ? w1[(size_t)l * 512 * 256 + r * 256 + k]
                        : w2[(size_t)l * 512 * 256 + (r - 512) * 256 + k];
    d[i] = __float2bfloat16(v);
}
__global__ void k_adb(const float* __restrict__ b1, const float* __restrict__ b2,
                      float* __restrict__ d) {
    int i = blockIdx.x * 256 + threadIdx.x;
    if (i >= 6144) return;
    int l = i >> 10, r = i & 1023;
    d[i] = (r < 512) ? b1[l * 512 + r] : b2[l * 512 + (r - 512)];
}

// ---------------- stroke embedding + layer-0 mod1 ----------------
__global__ void k_semb_mod(const float* __restrict__ strokes, const float* __restrict__ sp_w,
                           const float* __restrict__ sp_b, const float* __restrict__ pos,
                           const float* __restrict__ ssall,
                           bf16* __restrict__ x, bf16* __restrict__ x2)
{
    int row = blockIdx.x;
    int t = row % CT;
    int b = row / CT;
    __shared__ float st[8];
    __shared__ float red[2][8];
    __shared__ float stats[2];
    if (threadIdx.x < 8) st[threadIdx.x] = strokes[(size_t)row * 8 + threadIdx.x];
    __syncthreads();
    int d = threadIdx.x;
    float v = sp_b[d] + pos[t * CD + d];
    #pragma unroll
    for (int s = 0; s < 8; s++) v += st[s] * sp_w[d * 8 + s];
    x[(size_t)row * CD + d] = __float2bfloat16(v);

    float s = v, q = v * v;
    #pragma unroll
    for (int sh = 16; sh; sh >>= 1) {
        s += __shfl_xor_sync(0xffffffffu, s, sh);
        q += __shfl_xor_sync(0xffffffffu, q, sh);
    }
    if ((d & 31) == 0) { red[0][d >> 5] = s; red[1][d >> 5] = q; }
    __syncthreads();
    if (d == 0) {
        float a = 0.f, qq = 0.f;
        #pragma unroll
        for (int i = 0; i < 8; i++) { a += red[0][i]; qq += red[1][i]; }
        float mean = a * (1.f / 256.f);
        float var  = qq * (1.f / 256.f) - mean * mean;
        stats[0] = mean;
        stats[1] = rsqrtf(var + 1e-5f);
    }
    __syncthreads();
    const float* ssb = ssall + (size_t)b * 6144;   // layer 0, mod1: off = 0
    float xn = (v - stats[0]) * stats[1];
    x2[(size_t)row * CD + d] = __float2bfloat16((1.f + ssb[d]) * xn + ssb[256 + d]);
}

// ---------------- attention ----------------
__global__ void k_attn(const bf16* __restrict__ qkv, bf16* __restrict__ o)
{
    int bh = blockIdx.x;
    int b = bh >> 3, h = bh & 7;
    __shared__ float sq[CT][33], sk[CT][33], sv[CT][33], sp[CT][33];
    int tid = threadIdx.x;
    size_t base = (size_t)b * CT * 768 + h * 32;
    for (int idx = tid; idx < CT * 32; idx += 128) {
        int t = idx >> 5, d = idx & 31;
        size_t p = base + (size_t)t * 768 + d;
        sq[t][d] = __bfloat162float(qkv[p]);
        sk[t][d] = __bfloat162float(qkv[p + 256]);
        sv[t][d] = __bfloat162float(qkv[p + 512]);
    }
    __syncthreads();
    const float scale = 0.17677669529663687f;
    for (int idx = tid; idx < CT * CT; idx += 128) {
        int i = idx / CT, j = idx % CT;
        if (j <= i) {
            float s = 0.f;
            #pragma unroll
            for (int d = 0; d < 32; d++) s += sq[i][d] * sk[j][d];
            sp[i][j] = s * scale;
        }
    }
    __syncthreads();
    int lane = tid & 31, w = tid >> 5;
    for (int i = w; i < CT; i += 4) {
        float v = (lane <= i) ? sp[i][lane] : -1e30f;
        float mx = v;
        #pragma unroll
        for (int s = 16; s; s >>= 1) mx = fmaxf(mx, __shfl_xor_sync(0xffffffffu, mx, s));
        float e = (lane <= i) ? __expf(v - mx) : 0.f;
        float sum = e;
        #pragma unroll
        for (int s = 16; s; s >>= 1) sum += __shfl_xor_sync(0xffffffffu, sum, s);
        if (lane <= i) sp[i][lane] = e / sum;
    }
    __syncthreads();
    for (int idx = tid; idx < CT * 32; idx += 128) {
        int i = idx >> 5, d = idx & 31;
        float s = 0.f;
        for (int j = 0; j <= i; j++) s += sp[i][j] * sv[j][d];
        o[(size_t)(b * CT + i) * CD + h * 32 + d] = __float2bfloat16(s);
    }
}

// ---------------- final LN + flow-matching input ----------------
__global__ void k_final(const bf16* __restrict__ x, const float* __restrict__ on_g,
                        const float* __restrict__ on_b, const float* __restrict__ a_tar,
                        const float* __restrict__ a_src, const float* __restrict__ t,
                        bf16* __restrict__ xin)
{
    int b = blockIdx.x;
    const bf16* xr = x + ((size_t)b * CT + 29) * CD;
    __shared__ float rbuf[2][8];
    __shared__ float stats[2];
    int tid = threadIdx.x;
    float v = __bfloat162float(xr[tid]);
    float s = v, s2 = v * v;
    #pragma unroll
    for (int sh = 16; sh; sh >>= 1) {
        s  += __shfl_xor_sync(0xffffffffu, s, sh);
        s2 += __shfl_xor_sync(0xffffffffu, s2, sh);
    }
    if ((tid & 31) == 0) { rbuf[0][tid >> 5] = s; rbuf[1][tid >> 5] = s2; }
    __syncthreads();
    if (tid == 0) {
        float a = 0.f, q = 0.f;
        #pragma unroll
        for (int i = 0; i < 8; i++) { a += rbuf[0][i]; q += rbuf[1][i]; }
        float mean = a * (1.f / 256.f);
        float var  = q * (1.f / 256.f) - mean * mean;
        stats[0] = mean;
        stats[1] = rsqrtf(var + 1e-5f);
    }
    __syncthreads();
    float hn = (v - stats[0]) * stats[1] * on_g[tid] + on_b[tid];
    xin[(size_t)b * 320 + tid] = __float2bfloat16(hn);
    if (tid < 64) {
        int c = 256 + tid;
        float tv = t[b];
        float ov = 0.f;
        if (c < 264) {
            int i = c - 256;
            ov = (1.f - tv) * a_src[b * 8 + i] + tv * a_tar[b * 8 + i];
        } else if (c < 296) {
            int i = c - 264;
            int j = (i < 16) ? i : i - 16;
            float f = __expf(-9.210340371976184f * (float)j / 15.f);
            float a = tv * f;
            ov = (i < 16) ? sinf(a) : cosf(a);
        }
        xin[(size_t)b * 320 + c] = __float2bfloat16(ov);
    }
}

// ---------------- fm3 + loss ----------------
__global__ void k_fm3(const bf16* __restrict__ t2, const float* __restrict__ w3,
                      const float* __restrict__ b3, const float* __restrict__ a_tar,
                      const float* __restrict__ a_src, float* __restrict__ part)
{
    __shared__ float sw3[8 * 512];
    int tid = threadIdx.x;
    for (int i = tid; i < 8 * 512; i += 256) sw3[i] = w3[i];
    __syncthreads();
    int b = blockIdx.x * 256 + tid;
    float acc[8];
    #pragma unroll
    for (int o = 0; o < 8; o++) acc[o] = b3[o];
    const bf16* tr = t2 + (size_t)b * 512;
    for (int k = 0; k < 512; k++) {
        float tv = __bfloat162float(tr[k]);
        #pragma unroll
        for (int o = 0; o < 8; o++) acc[o] += tv * sw3[o * 512 + k];
    }
    float local = 0.f;
    #pragma unroll
    for (int o = 0; o < 8; o++) {
        float u = a_tar[b * 8 + o] - a_src[b * 8 + o];
        float d = acc[o] - u;
        local += d * d;
    }
    local *= (1.f / 65536.f);
    #pragma unroll
    for (int sh = 16; sh; sh >>= 1) local += __shfl_xor_sync(0xffffffffu, local, sh);
    __shared__ float rb[8];
    if ((tid & 31) == 0) rb[tid >> 5] = local;
    __syncthreads();
    if (tid == 0) {
        float s = 0.f;
        #pragma unroll
        for (int i = 0; i < 8; i++) s += rb[i];
        part[blockIdx.x] = s;
    }
}

__global__ void k_reduce(const float* __restrict__ part, float* __restrict__ out)
{
    float s = part[threadIdx.x];
    #pragma unroll
    for (int sh = 16; sh; sh >>= 1) s += __shfl_xor_sync(0xffffffffu, s, sh);
    if (threadIdx.x == 0) out[0] = s;
}

// ---------------- host side ------------------------------------------------
static void launch_gemm(int epi, const bf16* A, const bf16* W, const float* bias,
                        bf16* ob, float* of, int M, int N, int K)
{
    dim3 g(N / 128, M / 128);
    switch (epi) {
        case 0: k_gemm<0><<<g, 256, GEMM_SMEM>>>(A, W, bias, ob, of, M, N, K); break;
        case 1: k_gemm<1><<<g, 256, GEMM_SMEM>>>(A, W, bias, ob, of, M, N, K); break;
        default: k_gemm<3><<<g, 256, GEMM_SMEM>>>(A, W, bias, ob, of, M, N, K); break;
    }
}

#define GETSYM(var, sym) do { void* _p; cudaGetSymbolAddress(&_p, sym); var = (decltype(var))_p; } while (0)

extern "C" void kernel_launch(void* const* d_in, const int* in_sizes, int n_in,
                              void* d_out, int out_size)
{
    const float* strokes    = (const float*)d_in[0];
    const float* canvas     = (const float*)d_in[1];
    const float* a_tar      = (const float*)d_in[2];
    const float* a_src      = (const float*)d_in[3];
    const float* t_in       = (const float*)d_in[4];
    const float* ce_w1      = (const float*)d_in[5];
    const float* ce_b1      = (const float*)d_in[6];
    const float* ce_w2      = (const float*)d_in[7];
    const float* ce_b2      = (const float*)d_in[8];
    const float* sp_w       = (const float*)d_in[9];
    const float* sp_b       = (const float*)d_in[10];
    const float* pos_emb    = (const float*)d_in[11];
    const float* adaln1_w   = (const float*)d_in[12];
    const float* adaln1_b   = (const float*)d_in[13];
    const float* inproj_w   = (const float*)d_in[14];
    const float* inproj_b   = (const float*)d_in[15];
    const float* outproj_w  = (const float*)d_in[16];
    const float* outproj_b  = (const float*)d_in[17];
    const float* adaln2_w   = (const float*)d_in[18];
    const float* adaln2_b   = (const float*)d_in[19];
    const float* ff1_w      = (const float*)d_in[20];
    const float* ff1_b      = (const float*)d_in[21];
    const float* ff2_w      = (const float*)d_in[22];
    const float* ff2_b      = (const float*)d_in[23];
    const float* on_g       = (const float*)d_in[24];
    const float* on_b       = (const float*)d_in[25];
    const float* fm_w1      = (const float*)d_in[26];
    const float* fm_b1      = (const float*)d_in[27];
    const float* fm_w2      = (const float*)d_in[28];
    const float* fm_b2      = (const float*)d_in[29];
    const float* fm_w3      = (const float*)d_in[30];
    const float* fm_b3      = (const float*)d_in[31];
    float* out = (float*)d_out;
    (void)in_sizes; (void)n_in; (void)out_size;

    static int attr_done = 0;
    if (!attr_done) {
        cudaFuncSetAttribute(k_gemm<0>, cudaFuncAttributeMaxDynamicSharedMemorySize, GEMM_SMEM);
        cudaFuncSetAttribute(k_gemm<1>, cudaFuncAttributeMaxDynamicSharedMemorySize, GEMM_SMEM);
        cudaFuncSetAttribute(k_gemm<3>, cudaFuncAttributeMaxDynamicSharedMemorySize, GEMM_SMEM);
        cudaFuncSetAttribute(k_gemm_rm<0>, cudaFuncAttributeMaxDynamicSharedMemorySize, GEMMRM_SMEM);
        cudaFuncSetAttribute(k_gemm_rm<1>, cudaFuncAttributeMaxDynamicSharedMemorySize, GEMMRM_SMEM);
        attr_done = 1;
    }

    bf16 *p_canvas, *p_t1, *p_t2, *p_cv, *p_xb, *p_x2, *p_qkv, *p_ffh, *p_xin;
    bf16 *p_cew1, *p_cew2, *p_adw, *p_inp, *p_outp, *p_ff1, *p_ff2, *p_fw1, *p_fw2;
    float *p_ssall, *p_adb, *p_part;
    GETSYM(p_canvas, g_canvas); GETSYM(p_t1, g_t1); GETSYM(p_t2, g_t2b);
    GETSYM(p_cv, g_cv); GETSYM(p_xb, g_xb); GETSYM(p_x2, g_x2); GETSYM(p_qkv, g_qkv);
    GETSYM(p_ffh, g_ffh); GETSYM(p_xin, g_xin);
    GETSYM(p_cew1, g_ce_w1); GETSYM(p_cew2, g_ce_w2);
    GETSYM(p_adw, g_adw); GETSYM(p_adb, g_adb);
    GETSYM(p_inp, g_inp); GETSYM(p_outp, g_outp);
    GETSYM(p_ff1, g_ff1); GETSYM(p_ff2, g_ff2); GETSYM(p_fw1, g_fw1); GETSYM(p_fw2, g_fw2);
    GETSYM(p_ssall, g_ssall); GETSYM(p_part, g_part);

    auto conv = [](const float* s, bf16* d, int n) {
        k_convert<<<(n + 255) / 256, 256>>>(s, d, n);
    };

    conv(canvas,    p_canvas, CB * 384);
    conv(ce_w1,     p_cew1,   512 * 384);
    conv(ce_w2,     p_cew2,   256 * 512);
    conv(inproj_w,  p_inp,    CL * 768 * 256);
    conv(outproj_w, p_outp,   CL * 256 * 256);
    conv(ff1_w,     p_ff1,    CL * 1024 * 256);
    conv(ff2_w,     p_ff2,    CL * 256 * 1024);
    conv(fm_w2,     p_fw2,    512 * 512);
    k_convert_pad<<<(512 * 320 + 255) / 256, 256>>>(fm_w1, p_fw1);
    k_adw<<<(6144 * 256 + 255) / 256, 256>>>(adaln1_w, adaln2_w, p_adw);
    k_adb<<<(6144 + 255) / 256, 256>>>(adaln1_b, adaln2_b, p_adb);

    const int M = CB * CT;

    // context embedding
    launch_gemm(1, p_canvas, p_cew1, ce_b1, p_t1, nullptr, CB, 512, 384);
    launch_gemm(0, p_t1,     p_cew2, ce_b2, p_cv, nullptr, CB, 256, 512);

    // ALL adaLN scale/shift in one GEMM
    launch_gemm(3, p_cv, p_adw, p_adb, nullptr, p_ssall, CB, 6144, 256);

    // stroke embedding + layer-0 mod1 (bf16 x, bf16 x2)
    k_semb_mod<<<M, 256>>>(strokes, sp_w, sp_b, pos_emb, p_ssall, p_xb, p_x2);

    for (int l = 0; l < CL; l++) {
        // qkv from modulated x2
        launch_gemm(0, p_x2, p_inp + (size_t)l * 768 * 256, inproj_b + l * 768,
                    p_qkv, nullptr, M, 768, 256);
        k_attn<<<CB * 8, 128>>>(p_qkv, p_x2);
        // outproj: x += o@W^T + b ; x2 = mod2 (for ff1)
        k_gemm_rm<1><<<M / 128, 512, GEMMRM_SMEM>>>(
            p_x2, p_outp + (size_t)l * 256 * 256, outproj_b + l * 256,
            p_xb, p_x2, p_ssall, l * 1024 + 512, M, 256);
        // ff1
        launch_gemm(1, p_x2, p_ff1 + (size_t)l * 1024 * 256, ff1_b + l * 1024,
                    p_ffh, nullptr, M, 1024, 256);
        // ff2: x += ffh@W^T + b ; x2 = next layer's mod1 (except last layer)
        if (l < CL - 1) {
            k_gemm_rm<1><<<M / 128, 512, GEMMRM_SMEM>>>(
                p_ffh, p_ff2 + (size_t)l * 256 * 1024, ff2_b + l * 256,
                p_xb, p_x2, p_ssall, (l + 1) * 1024, M, 1024);
        } else {
            k_gemm_rm<0><<<M / 128, 512, GEMMRM_SMEM>>>(
                p_ffh, p_ff2 + (size_t)l * 256 * 1024, ff2_b + l * 256,
                p_xb, p_x2, p_ssall, 0, M, 1024);
        }
    }

    // final LN + flow-matching head
    k_final<<<CB, 256>>>(p_xb, on_g, on_b, a_tar, a_src, t_in, p_xin);
    launch_gemm(1, p_xin, p_fw1, fm_b1, p_t1, nullptr, CB, 512, 320);
    launch_gemm(1, p_t1,  p_fw2, fm_b2, p_t2, nullptr, CB, 512, 512);
    k_fm3<<<32, 256>>>(p_t2, fm_w3, fm_b3, a_tar, a_src, p_part);
    k_reduce<<<1, 32>>>(p_part, out);
}